// round 12
// baseline (speedup 1.0000x reference)
#include <cuda_runtime.h>
#include <cuda_fp16.h>
#include <math.h>
#include <stdint.h>

// Problem constants: B=2, L=2048, D=1024, H=16, hd=64
#define Bsz 2
#define Lsz 2048
#define Dsz 1024
#define Hsz 16
#define HDsz 64

#define NQKV (Bsz * Hsz * Lsz * HDsz)   // 4194304
#define NX   (Bsz * Lsz * Dsz)          // 4194304
#define NW   (Dsz * Dsz)                // 1048576 = 2^20

#define NQT (Lsz / 128)                 // 16 q-tiles
#define NITEMS (NQT * Bsz * Hsz)        // 512 work items
#define FLASH_CTAS 296                  // 2 per SM x 148 SMs

// ---------------- device scratch ------------------------------------------
__device__ __half g_xh[NX],  g_xl[NX];
__device__ __half g_w[4 * NW];                  // wq,wk,wv,wo single fp16
__device__ __half g_qh[NQKV], g_ql[NQKV];
__device__ __half g_k[NQKV];                    // single fp16 (post-RoPE)
__device__ __half g_v[NQKV];                    // single fp16
__device__ __half g_aoh[NX], g_aol[NX];
__device__ int g_wctr;                          // flash work-queue counter

// ---------------- helpers --------------------------------------------------
__device__ __forceinline__ void sh2(float x, __half& h, __half& l) {
    h = __float2half_rn(x);
    l = __float2half_rn(x - __half2float(h));
}
__device__ __forceinline__ uint32_t packh(__half a, __half b) {
    uint16_t au = *(uint16_t*)&a, bu = *(uint16_t*)&b;
    return (uint32_t)au | ((uint32_t)bu << 16);
}

__device__ __forceinline__ void mma16(float c[4], const uint32_t a[4], const uint32_t b[2]) {
    asm volatile(
        "mma.sync.aligned.m16n8k16.row.col.f32.f16.f16.f32 "
        "{%0,%1,%2,%3}, {%4,%5,%6,%7}, {%8,%9}, {%0,%1,%2,%3};\n"
        : "+f"(c[0]), "+f"(c[1]), "+f"(c[2]), "+f"(c[3])
        : "r"(a[0]), "r"(a[1]), "r"(a[2]), "r"(a[3]), "r"(b[0]), "r"(b[1]));
}

__device__ __forceinline__ void ldsm_x2_trans(uint32_t& r0, uint32_t& r1, uint32_t addr) {
    asm volatile("ldmatrix.sync.aligned.m8n8.x2.trans.shared.b16 {%0,%1}, [%2];"
                 : "=r"(r0), "=r"(r1) : "r"(addr));
}

__device__ __forceinline__ void cp16(uint32_t dst, const void* src) {
    asm volatile("cp.async.cg.shared.global [%0],[%1],16;\n" ::"r"(dst), "l"(src) : "memory");
}
__device__ __forceinline__ void cpcommit() { asm volatile("cp.async.commit_group;\n" ::: "memory"); }
__device__ __forceinline__ void cpwait1()  { asm volatile("cp.async.wait_group 1;\n" ::: "memory"); }
__device__ __forceinline__ void cpwait0()  { asm volatile("cp.async.wait_group 0;\n" ::: "memory"); }

// ---------------- split kernels -------------------------------------------
__global__ void split_x_kernel(const float* __restrict__ in) {
    int i = blockIdx.x * blockDim.x + threadIdx.x;
    if (i == 0) g_wctr = 0;             // reset flash work queue every launch
    float2 v = *(const float2*)(in + 2 * (size_t)i);
    __half h0, l0, h1, l1;
    sh2(v.x, h0, l0); sh2(v.y, h1, l1);
    ((uint32_t*)g_xh)[i] = packh(h0, h1);
    ((uint32_t*)g_xl)[i] = packh(l0, l1);
}

__global__ void split_w_kernel(const float* __restrict__ wq,
                               const float* __restrict__ wk,
                               const float* __restrict__ wv,
                               const float* __restrict__ wo) {
    int i = blockIdx.x * blockDim.x + threadIdx.x;
    size_t e = 2 * (size_t)i;
    int m = (int)(e >> 20);
    int r = (int)(e & (NW - 1));
    const float* src = (m == 0) ? wq : (m == 1) ? wk : (m == 2) ? wv : wo;
    float2 v = *(const float2*)(src + r);
    ((uint32_t*)g_w)[((size_t)m * NW + r) >> 1] =
        packh(__float2half_rn(v.x), __float2half_rn(v.y));
}

// ---------------- fp16x2 projection GEMM (128x128 CTA, 256 thr, 2 CTA/SM) --
// 8 warps (2M x 4N); warp tile 64x32 with N-tiles strided 32 (RoPE pairs stay
// thread-local). BK=32, 3-stage cp.async pipeline. Accumulation order per
// output element identical to R11 -> bitwise-identical results.
#define PSTR 40
#define PA_ELEMS (128 * PSTR)                     // 5120 halves per plane
#define PSTAGE_ELEMS (3 * PA_ELEMS)               // Ah, Al, B = 15360 halves
#define PSTAGE_BYTES (PSTAGE_ELEMS * 2)           // 30720
#define PROJ_SMEM (3 * PSTAGE_BYTES)              // 92160 bytes -> 2 CTA/SM

__device__ __forceinline__ void proj_mainloop(const __half* __restrict__ Agh,
                                              const __half* __restrict__ Agl,
                                              const __half* __restrict__ Bg,
                                              float C[4][4][4], __half* sm) {
    const int tid = threadIdx.x;
    const int wid = tid >> 5, lane = tid & 31;
    const int g = lane >> 2, t = lane & 3;
    const int wm = (wid >> 2) * 64;               // 0 or 64
    const int wnb = (wid & 3) * 8;                // N base 0,8,16,24 (stride 32 per nt)

    auto load_chunk = [&](int c, int s) {
        __half* st = sm + s * PSTAGE_ELEMS;
        // A hi/lo planes: 128 rows x 32 cols each (512 cp16 per plane)
#pragma unroll
        for (int p = 0; p < 2; p++) {
            const __half* gp = (p == 0) ? Agh : Agl;
            __half* sp = st + p * PA_ELEMS;
#pragma unroll
            for (int i = 0; i < 2; i++) {
                int idx = tid + 256 * i;
                int row = idx >> 2, q = idx & 3;
                cp16((uint32_t)__cvta_generic_to_shared(sp + row * PSTR + q * 8),
                     gp + (size_t)row * Dsz + c * 32 + q * 8);
            }
        }
        // B single plane: 128 rows x 32 cols
        {
            __half* sp = st + 2 * PA_ELEMS;
#pragma unroll
            for (int i = 0; i < 2; i++) {
                int idx = tid + 256 * i;
                int row = idx >> 2, q = idx & 3;
                cp16((uint32_t)__cvta_generic_to_shared(sp + row * PSTR + q * 8),
                     Bg + (size_t)row * Dsz + c * 32 + q * 8);
            }
        }
    };

    const int NCH = Dsz / 32;
    load_chunk(0, 0); cpcommit();
    load_chunk(1, 1); cpcommit();

    for (int c = 0; c < NCH; c++) {
        if (c == NCH - 1) cpwait0(); else cpwait1();
        __syncthreads();
        if (c + 2 < NCH) { load_chunk(c + 2, (c + 2) % 3); cpcommit(); }

        const __half* st = sm + (c % 3) * PSTAGE_ELEMS;
        const __half* sAh = st;
        const __half* sAl = st + PA_ELEMS;
        const __half* sB  = st + 2 * PA_ELEMS;

#pragma unroll
        for (int ks = 0; ks < 2; ks++) {
            const int kb = ks * 16 + 2 * t;
            uint32_t bh[4][2];
#pragma unroll
            for (int nt = 0; nt < 4; nt++) {
                const __half* bp = sB + (wnb + nt * 32 + g) * PSTR + kb;
                bh[nt][0] = *(const uint32_t*)bp;
                bh[nt][1] = *(const uint32_t*)(bp + 8);
            }
#pragma unroll
            for (int mt = 0; mt < 4; mt++) {
                const int ar = wm + mt * 16 + g;
                const __half* ap = sAh + ar * PSTR + kb;
                const __half* aq = sAl + ar * PSTR + kb;
                uint32_t ah[4], al[4];
                ah[0] = *(const uint32_t*)ap;
                ah[1] = *(const uint32_t*)(ap + 8 * PSTR);
                ah[2] = *(const uint32_t*)(ap + 8);
                ah[3] = *(const uint32_t*)(ap + 8 * PSTR + 8);
                al[0] = *(const uint32_t*)aq;
                al[1] = *(const uint32_t*)(aq + 8 * PSTR);
                al[2] = *(const uint32_t*)(aq + 8);
                al[3] = *(const uint32_t*)(aq + 8 * PSTR + 8);
#pragma unroll
                for (int nt = 0; nt < 4; nt++) {
                    mma16(C[mt][nt], ah, bh[nt]);
                    mma16(C[mt][nt], al, bh[nt]);
                }
            }
        }
    }
}

// ---------------- QKV projection with fused RoPE + Q scale -----------------
__global__ void __launch_bounds__(256, 2) qkv_f16_kernel(const float* __restrict__ cosp,
                                                         const float* __restrict__ sinp) {
    extern __shared__ __half smh[];
    const int z = blockIdx.z;
    const int rowBase = blockIdx.y * 128;
    const int colBase = blockIdx.x * 128;

    float C[4][4][4];
#pragma unroll
    for (int a = 0; a < 4; a++)
#pragma unroll
        for (int b = 0; b < 4; b++)
#pragma unroll
            for (int c = 0; c < 4; c++) C[a][b][c] = 0.f;

    proj_mainloop(g_xh + (size_t)rowBase * Dsz, g_xl + (size_t)rowBase * Dsz,
                  g_w + (size_t)z * NW + (size_t)colBase * Dsz, C, smh);

    const int tid = threadIdx.x;
    const int wid = tid >> 5, lane = tid & 31;
    const int g = lane >> 2, t = lane & 3;
    const int wm = (wid >> 2) * 64;
    const int wnb = (wid & 3) * 8;

    // fused RoPE: cols d and d+32 live in C[mt][np] / C[mt][np+1] (np = 0, 2)
    if (z <= 1) {
#pragma unroll
        for (int mt = 0; mt < 4; mt++) {
            int r = rowBase + wm + mt * 16 + g;
            int l0 = r & (Lsz - 1);
#pragma unroll
            for (int np = 0; np < 4; np += 2) {
#pragma unroll
                for (int e = 0; e < 4; e++) {
                    int dd = wnb + 2 * t + (e & 1);          // 0..31
                    int ll = (e < 2) ? l0 : (l0 + 8);
                    float c1 = cosp[ll * HDsz + dd];
                    float s1 = sinp[ll * HDsz + dd];
                    float c2 = cosp[ll * HDsz + dd + 32];
                    float s2 = sinp[ll * HDsz + dd + 32];
                    float x1 = C[mt][np][e], x2 = C[mt][np + 1][e];
                    C[mt][np][e]     = x1 * c1 - x2 * s1;
                    C[mt][np + 1][e] = x2 * c2 + x1 * s2;
                }
            }
        }
    }
    if (z == 0) {   // fold 1/sqrt(hd) into q (exact power of two)
#pragma unroll
        for (int mt = 0; mt < 4; mt++)
#pragma unroll
            for (int nt = 0; nt < 4; nt++)
#pragma unroll
                for (int e = 0; e < 4; e++) C[mt][nt][e] *= 0.125f;
    }

#pragma unroll
    for (int mt = 0; mt < 4; mt++) {
#pragma unroll
        for (int nt = 0; nt < 4; nt++) {
            int r = rowBase + wm + mt * 16 + g;
            int n = colBase + wnb + nt * 32 + 2 * t;
            int h = n >> 6, d = n & 63;
            int b = r >> 11, l = r & 2047;
            size_t o0 = (((size_t)(b * Hsz + h) * Lsz + l) * HDsz + d);
            size_t o1 = (((size_t)(b * Hsz + h) * Lsz + (l + 8)) * HDsz + d);
            if (z == 0) {           // q: split hi/lo
                __half h0, l0h, h1, l1h;
                sh2(C[mt][nt][0], h0, l0h); sh2(C[mt][nt][1], h1, l1h);
                *(uint32_t*)(g_qh + o0) = packh(h0, h1);
                *(uint32_t*)(g_ql + o0) = packh(l0h, l1h);
                sh2(C[mt][nt][2], h0, l0h); sh2(C[mt][nt][3], h1, l1h);
                *(uint32_t*)(g_qh + o1) = packh(h0, h1);
                *(uint32_t*)(g_ql + o1) = packh(l0h, l1h);
            } else {                // k, v: single fp16
                __half* dst = (z == 1) ? g_k : g_v;
                *(uint32_t*)(dst + o0) =
                    packh(__float2half_rn(C[mt][nt][0]), __float2half_rn(C[mt][nt][1]));
                *(uint32_t*)(dst + o1) =
                    packh(__float2half_rn(C[mt][nt][2]), __float2half_rn(C[mt][nt][3]));
            }
        }
    }
}

// ---------------- Output projection (writes fp32 out) ----------------------
__global__ void __launch_bounds__(256, 2) oproj_f16_kernel(float* __restrict__ out) {
    extern __shared__ __half smh[];
    const int rowBase = blockIdx.y * 128;
    const int colBase = blockIdx.x * 128;

    float C[4][4][4];
#pragma unroll
    for (int a = 0; a < 4; a++)
#pragma unroll
        for (int b = 0; b < 4; b++)
#pragma unroll
            for (int c = 0; c < 4; c++) C[a][b][c] = 0.f;

    proj_mainloop(g_aoh + (size_t)rowBase * Dsz, g_aol + (size_t)rowBase * Dsz,
                  g_w + (size_t)3 * NW + (size_t)colBase * Dsz, C, smh);

    const int tid = threadIdx.x;
    const int wid = tid >> 5, lane = tid & 31;
    const int g = lane >> 2, t = lane & 3;
    const int wm = (wid >> 2) * 64;
    const int wnb = (wid & 3) * 8;
#pragma unroll
    for (int mt = 0; mt < 4; mt++) {
#pragma unroll
        for (int nt = 0; nt < 4; nt++) {
            int r = rowBase + wm + mt * 16 + g;
            int n = colBase + wnb + nt * 32 + 2 * t;
            *(float2*)(out + (size_t)r * Dsz + n) = make_float2(C[mt][nt][0], C[mt][nt][1]);
            *(float2*)(out + (size_t)(r + 8) * Dsz + n) = make_float2(C[mt][nt][2], C[mt][nt][3]);
        }
    }
}

// ---------------- Flash attention: fp16x2, persistent + work queue ---------
#define FSTRB 72
#define OFF_QH 0
#define OFF_QL (128 * FSTRB)
#define OFF_KV0 (2 * 128 * FSTRB)
#define KV_PLANE (64 * FSTRB)
#define KV_STAGE (2 * KV_PLANE)                  // K single + V single
#define FLASH_ELEMS (OFF_KV0 + 2 * KV_STAGE)
#define FLASH_SMEM (FLASH_ELEMS * 2 + 16)        // +16 for s_item slot

__global__ void __launch_bounds__(256, 2) flashmma_kernel() {
    extern __shared__ __half smh[];
    __half* Qh = smh + OFF_QH;
    __half* Ql = smh + OFF_QL;
    int* s_item = (int*)(smh + FLASH_ELEMS);

    const int tid = threadIdx.x;
    const int wid = tid >> 5, lane = tid & 31;
    const int g = lane >> 2, t = lane & 3;
    const int vln = lane & 15;
    const int pr = wid * 16 + g;

    for (;;) {
        __syncthreads();
        if (tid == 0) *s_item = atomicAdd(&g_wctr, 1);
        __syncthreads();
        const int item = *s_item;
        if (item >= NITEMS) break;

        const int qt = NQT - 1 - (item >> 5);   // biggest-first
        const int bh = item & 31;
        const int q0 = qt * 128;
        const size_t base = (size_t)bh * Lsz * HDsz;

        // ---- Q tile (hi/lo) ----
#pragma unroll
        for (int i = 0; i < 4; i++) {
            int idx = tid + 256 * i;
            int row = idx >> 3;
            int c8 = (idx & 7) * 8;
            size_t go = base + (size_t)(q0 + row) * HDsz + c8;
            *(float4*)(Qh + row * FSTRB + c8) = *(const float4*)(g_qh + go);
            *(float4*)(Ql + row * FSTRB + c8) = *(const float4*)(g_ql + go);
        }

        auto loadKV = [&](int kt2, int s) {
            __half* st = smh + OFF_KV0 + s * KV_STAGE;
            const int j0 = kt2 * 64;
#pragma unroll
            for (int p = 0; p < 2; p++) {
                const __half* gp = (p == 0) ? g_k : g_v;
#pragma unroll
                for (int i = 0; i < 2; i++) {
                    int idx = tid + 256 * i;
                    int row = idx >> 3;
                    int c8 = (idx & 7) * 8;
                    cp16((uint32_t)__cvta_generic_to_shared(st + p * KV_PLANE + row * FSTRB + c8),
                         gp + base + (size_t)(j0 + row) * HDsz + c8);
                }
            }
        };

        float O[8][4];
#pragma unroll
        for (int i = 0; i < 8; i++)
#pragma unroll
            for (int j = 0; j < 4; j++) O[i][j] = 0.f;
        float mr[2] = {-1e30f, -1e30f};
        float lr[2] = {0.f, 0.f};

        const int nkt = 2 * qt + 2;
        loadKV(0, 0); cpcommit();

        for (int kt = 0; kt < nkt; kt++) {
            const int s = kt & 1;
            const int j0 = kt * 64;
            __syncthreads();
            if (kt + 1 < nkt) { loadKV(kt + 1, s ^ 1); cpcommit(); cpwait1(); }
            else              { cpwait0(); }
            __syncthreads();

            const __half* Ks = smh + OFF_KV0 + s * KV_STAGE;
            const __half* Vs = Ks + KV_PLANE;
            const uint32_t v_u32 = (uint32_t)__cvta_generic_to_shared(Vs);

            // ---- GEMM1: S = Q @ K^T (fp16x2: Qh,Ql vs K single) ----
            float S[8][4];
#pragma unroll
            for (int i = 0; i < 8; i++)
#pragma unroll
                for (int j = 0; j < 4; j++) S[i][j] = 0.f;

#pragma unroll
            for (int ks = 0; ks < 4; ks++) {
                const int kb = ks * 16 + 2 * t;
                const __half* ap = Qh + pr * FSTRB + kb;
                const __half* aq = Ql + pr * FSTRB + kb;
                uint32_t ah[4], al[4];
                ah[0] = *(const uint32_t*)ap;
                ah[1] = *(const uint32_t*)(ap + 8 * FSTRB);
                ah[2] = *(const uint32_t*)(ap + 8);
                ah[3] = *(const uint32_t*)(ap + 8 * FSTRB + 8);
                al[0] = *(const uint32_t*)aq;
                al[1] = *(const uint32_t*)(aq + 8 * FSTRB);
                al[2] = *(const uint32_t*)(aq + 8);
                al[3] = *(const uint32_t*)(aq + 8 * FSTRB + 8);
#pragma unroll
                for (int nt = 0; nt < 8; nt++) {
                    const __half* kp = Ks + (nt * 8 + g) * FSTRB + kb;
                    uint32_t bh2[2] = {*(const uint32_t*)kp, *(const uint32_t*)(kp + 8)};
                    mma16(S[nt], ah, bh2);
                    mma16(S[nt], al, bh2);
                }
            }

            // ---- causal mask (diagonal tiles only) ----
            if (kt >= 2 * qt) {
                int r0g = q0 + pr;
#pragma unroll
                for (int nt = 0; nt < 8; nt++) {
                    int c0 = j0 + nt * 8 + 2 * t;
                    if (c0 > r0g)         S[nt][0] = -1e30f;
                    if (c0 + 1 > r0g)     S[nt][1] = -1e30f;
                    if (c0 > r0g + 8)     S[nt][2] = -1e30f;
                    if (c0 + 1 > r0g + 8) S[nt][3] = -1e30f;
                }
            }

            // ---- online softmax ----
#pragma unroll
            for (int h2 = 0; h2 < 2; h2++) {
                float mloc = -1e30f;
#pragma unroll
                for (int nt = 0; nt < 8; nt++)
                    mloc = fmaxf(mloc, fmaxf(S[nt][2 * h2], S[nt][2 * h2 + 1]));
                mloc = fmaxf(mloc, __shfl_xor_sync(0xffffffffu, mloc, 1));
                mloc = fmaxf(mloc, __shfl_xor_sync(0xffffffffu, mloc, 2));
                float mnew = fmaxf(mr[h2], mloc);
                float sc = __expf(mr[h2] - mnew);
                float ls = 0.f;
#pragma unroll
                for (int nt = 0; nt < 8; nt++) {
                    float p0 = __expf(S[nt][2 * h2] - mnew);
                    float p1 = __expf(S[nt][2 * h2 + 1] - mnew);
                    S[nt][2 * h2] = p0; S[nt][2 * h2 + 1] = p1;
                    ls += p0 + p1;
                }
                ls += __shfl_xor_sync(0xffffffffu, ls, 1);
                ls += __shfl_xor_sync(0xffffffffu, ls, 2);
                lr[h2] = lr[h2] * sc + ls;
                mr[h2] = mnew;
#pragma unroll
                for (int nt = 0; nt < 8; nt++) {
                    O[nt][2 * h2] *= sc;
                    O[nt][2 * h2 + 1] *= sc;
                }
            }

            // ---- GEMM2: O += P @ V (P split hi/lo in regs, V single) ----
#pragma unroll
            for (int ks = 0; ks < 4; ks++) {
                uint32_t ah[4], al[4];
                {
                    __half h0, l0h, h1, l1h;
                    sh2(S[2 * ks][0], h0, l0h);     sh2(S[2 * ks][1], h1, l1h);
                    ah[0] = packh(h0, h1);          al[0] = packh(l0h, l1h);
                    sh2(S[2 * ks][2], h0, l0h);     sh2(S[2 * ks][3], h1, l1h);
                    ah[1] = packh(h0, h1);          al[1] = packh(l0h, l1h);
                    sh2(S[2 * ks + 1][0], h0, l0h); sh2(S[2 * ks + 1][1], h1, l1h);
                    ah[2] = packh(h0, h1);          al[2] = packh(l0h, l1h);
                    sh2(S[2 * ks + 1][2], h0, l0h); sh2(S[2 * ks + 1][3], h1, l1h);
                    ah[3] = packh(h0, h1);          al[3] = packh(l0h, l1h);
                }
                const uint32_t rowoff = ((ks * 16 + vln) * FSTRB) * 2;
#pragma unroll
                for (int dt = 0; dt < 8; dt++) {
                    uint32_t bh2[2];
                    ldsm_x2_trans(bh2[0], bh2[1], v_u32 + rowoff + dt * 16);
                    mma16(O[dt], ah, bh2);
                    mma16(O[dt], al, bh2);
                }
            }
        }

        // ---- epilogue: normalize, split, write ao planes ----
        const float i0 = 1.f / lr[0];
        const float i1 = 1.f / lr[1];
        const int r = q0 + pr;
        const int b = bh >> 4;
        const int h = bh & 15;
        const size_t ob = (size_t)b * Lsz * Dsz + (size_t)h * HDsz;
#pragma unroll
        for (int dt = 0; dt < 8; dt++) {
            int d = dt * 8 + 2 * t;
            __half h0, l0h, h1, l1h;
            sh2(O[dt][0] * i0, h0, l0h); sh2(O[dt][1] * i0, h1, l1h);
            *(uint32_t*)(g_aoh + ob + (size_t)r * Dsz + d) = packh(h0, h1);
            *(uint32_t*)(g_aol + ob + (size_t)r * Dsz + d) = packh(l0h, l1h);
            sh2(O[dt][2] * i1, h0, l0h); sh2(O[dt][3] * i1, h1, l1h);
            *(uint32_t*)(g_aoh + ob + (size_t)(r + 8) * Dsz + d) = packh(h0, h1);
            *(uint32_t*)(g_aol + ob + (size_t)(r + 8) * Dsz + d) = packh(l0h, l1h);
        }
    }
}

// ---------------------------------------------------------------------------
extern "C" void kernel_launch(void* const* d_in, const int* in_sizes, int n_in,
                              void* d_out, int out_size) {
    (void)in_sizes; (void)n_in; (void)out_size;
    const float* x    = (const float*)d_in[0];
    const float* cosp = (const float*)d_in[1];
    const float* sinp = (const float*)d_in[2];
    const float* wq   = (const float*)d_in[3];
    const float* wk   = (const float*)d_in[4];
    const float* wv   = (const float*)d_in[5];
    const float* wo   = (const float*)d_in[6];
    float* out = (float*)d_out;

    cudaFuncSetAttribute(qkv_f16_kernel,
                         cudaFuncAttributeMaxDynamicSharedMemorySize, PROJ_SMEM);
    cudaFuncSetAttribute(oproj_f16_kernel,
                         cudaFuncAttributeMaxDynamicSharedMemorySize, PROJ_SMEM);
    cudaFuncSetAttribute(flashmma_kernel,
                         cudaFuncAttributeMaxDynamicSharedMemorySize, FLASH_SMEM);

    // 1) split inputs (also resets flash work queue)
    split_x_kernel<<<(NX / 2) / 256, 256>>>(x);
    split_w_kernel<<<(4 * NW / 2) / 256, 256>>>(wq, wk, wv, wo);

    // 2) QKV projections with fused RoPE + q-scale -> q (hi/lo), k, v planes
    qkv_f16_kernel<<<dim3(Dsz / 128, (Bsz * Lsz) / 128, 3), 256, PROJ_SMEM>>>(cosp, sinp);

    // 3) causal flash attention (persistent, work-queue balanced) -> ao planes
    flashmma_kernel<<<FLASH_CTAS, 256, FLASH_SMEM>>>();

    // 4) output projection -> d_out
    oproj_f16_kernel<<<dim3(Dsz / 128, (Bsz * Lsz) / 128), 256, PROJ_SMEM>>>(out);
}

// round 14
// speedup vs baseline: 1.0999x; 1.0999x over previous
#include <cuda_runtime.h>
#include <cuda_fp16.h>
#include <math.h>
#include <stdint.h>

// Problem constants: B=2, L=2048, D=1024, H=16, hd=64
#define Bsz 2
#define Lsz 2048
#define Dsz 1024
#define Hsz 16
#define HDsz 64

#define NQKV (Bsz * Hsz * Lsz * HDsz)   // 4194304
#define NX   (Bsz * Lsz * Dsz)          // 4194304
#define NW   (Dsz * Dsz)                // 1048576 = 2^20

#define NQT (Lsz / 128)                 // 16 q-tiles
#define NITEMS (NQT * Bsz * Hsz)        // 512 work items
#define FLASH_CTAS 296                  // 2 per SM x 148 SMs

// ---------------- device scratch ------------------------------------------
__device__ __half g_xh[NX],  g_xl[NX];
__device__ __half g_w[4 * NW];                  // wq,wk,wv,wo single fp16
__device__ __half g_qh[NQKV], g_ql[NQKV];
__device__ __half g_k[NQKV];                    // single fp16 (post-RoPE)
__device__ __half g_v[NQKV];                    // single fp16
__device__ __half g_aoh[NX], g_aol[NX];
__device__ int g_wctr;                          // flash work-queue counter

// ---------------- helpers --------------------------------------------------
__device__ __forceinline__ void sh2(float x, __half& h, __half& l) {
    h = __float2half_rn(x);
    l = __float2half_rn(x - __half2float(h));
}
__device__ __forceinline__ uint32_t packh(__half a, __half b) {
    uint16_t au = *(uint16_t*)&a, bu = *(uint16_t*)&b;
    return (uint32_t)au | ((uint32_t)bu << 16);
}

__device__ __forceinline__ void mma16(float c[4], const uint32_t a[4], const uint32_t b[2]) {
    asm volatile(
        "mma.sync.aligned.m16n8k16.row.col.f32.f16.f16.f32 "
        "{%0,%1,%2,%3}, {%4,%5,%6,%7}, {%8,%9}, {%0,%1,%2,%3};\n"
        : "+f"(c[0]), "+f"(c[1]), "+f"(c[2]), "+f"(c[3])
        : "r"(a[0]), "r"(a[1]), "r"(a[2]), "r"(a[3]), "r"(b[0]), "r"(b[1]));
}

__device__ __forceinline__ void ldsm_x2_trans(uint32_t& r0, uint32_t& r1, uint32_t addr) {
    asm volatile("ldmatrix.sync.aligned.m8n8.x2.trans.shared.b16 {%0,%1}, [%2];"
                 : "=r"(r0), "=r"(r1) : "r"(addr));
}

__device__ __forceinline__ void cp16(uint32_t dst, const void* src) {
    asm volatile("cp.async.cg.shared.global [%0],[%1],16;\n" ::"r"(dst), "l"(src) : "memory");
}
__device__ __forceinline__ void cpcommit() { asm volatile("cp.async.commit_group;\n" ::: "memory"); }
__device__ __forceinline__ void cpwait1()  { asm volatile("cp.async.wait_group 1;\n" ::: "memory"); }
__device__ __forceinline__ void cpwait0()  { asm volatile("cp.async.wait_group 0;\n" ::: "memory"); }

// ---------------- split kernels -------------------------------------------
__global__ void split_x_kernel(const float* __restrict__ in) {
    int i = blockIdx.x * blockDim.x + threadIdx.x;
    if (i == 0) g_wctr = 0;             // reset flash work queue every launch
    float2 v = *(const float2*)(in + 2 * (size_t)i);
    __half h0, l0, h1, l1;
    sh2(v.x, h0, l0); sh2(v.y, h1, l1);
    ((uint32_t*)g_xh)[i] = packh(h0, h1);
    ((uint32_t*)g_xl)[i] = packh(l0, l1);
}

__global__ void split_w_kernel(const float* __restrict__ wq,
                               const float* __restrict__ wk,
                               const float* __restrict__ wv,
                               const float* __restrict__ wo) {
    int i = blockIdx.x * blockDim.x + threadIdx.x;
    size_t e = 2 * (size_t)i;
    int m = (int)(e >> 20);
    int r = (int)(e & (NW - 1));
    const float* src = (m == 0) ? wq : (m == 1) ? wk : (m == 2) ? wv : wo;
    float2 v = *(const float2*)(src + r);
    ((uint32_t*)g_w)[((size_t)m * NW + r) >> 1] =
        packh(__float2half_rn(v.x), __float2half_rn(v.y));
}

// ---------------- fp16x2 projection GEMM (128x256 CTA, 256 threads) --------
#define PSTR 40
#define PA_ELEMS (128 * PSTR)                     // 5120
#define PB_ELEMS (256 * PSTR)                     // 10240
#define PSTAGE_ELEMS (2 * PA_ELEMS + PB_ELEMS)    // 20480 halves
#define PSTAGE_BYTES (PSTAGE_ELEMS * 2)           // 40960
#define PROJ_SMEM (3 * PSTAGE_BYTES)              // 122880 bytes

__device__ __forceinline__ void proj_mainloop(const __half* __restrict__ Agh,
                                              const __half* __restrict__ Agl,
                                              const __half* __restrict__ Bg,
                                              float C[4][8][4], __half* sm) {
    const int tid = threadIdx.x;
    const int wid = tid >> 5, lane = tid & 31;
    const int g = lane >> 2, t = lane & 3;
    const int wm = (wid >> 2) * 64;
    const int wn = (wid & 3) * 64;

    auto load_chunk = [&](int c, int s) {
        __half* st = sm + s * PSTAGE_ELEMS;
#pragma unroll
        for (int p = 0; p < 2; p++) {
            const __half* gp = (p == 0) ? Agh : Agl;
            __half* sp = st + p * PA_ELEMS;
#pragma unroll
            for (int i = 0; i < 2; i++) {
                int idx = tid + 256 * i;
                int row = idx >> 2, q = idx & 3;
                cp16((uint32_t)__cvta_generic_to_shared(sp + row * PSTR + q * 8),
                     gp + (size_t)row * Dsz + c * 32 + q * 8);
            }
        }
        {
            __half* sp = st + 2 * PA_ELEMS;
#pragma unroll
            for (int i = 0; i < 4; i++) {
                int idx = tid + 256 * i;
                int row = idx >> 2, q = idx & 3;
                cp16((uint32_t)__cvta_generic_to_shared(sp + row * PSTR + q * 8),
                     Bg + (size_t)row * Dsz + c * 32 + q * 8);
            }
        }
    };

    const int NCH = Dsz / 32;
    load_chunk(0, 0); cpcommit();
    load_chunk(1, 1); cpcommit();

    for (int c = 0; c < NCH; c++) {
        if (c == NCH - 1) cpwait0(); else cpwait1();
        __syncthreads();
        if (c + 2 < NCH) { load_chunk(c + 2, (c + 2) % 3); cpcommit(); }

        const __half* st = sm + (c % 3) * PSTAGE_ELEMS;
        const __half* sAh = st;
        const __half* sAl = st + PA_ELEMS;
        const __half* sB  = st + 2 * PA_ELEMS;

#pragma unroll
        for (int ks = 0; ks < 2; ks++) {
            const int kb = ks * 16 + 2 * t;
            uint32_t bh[8][2];
#pragma unroll
            for (int nt = 0; nt < 8; nt++) {
                const __half* bp = sB + (wn + nt * 8 + g) * PSTR + kb;
                bh[nt][0] = *(const uint32_t*)bp;
                bh[nt][1] = *(const uint32_t*)(bp + 8);
            }
#pragma unroll
            for (int mt = 0; mt < 4; mt++) {
                const int ar = wm + mt * 16 + g;
                const __half* ap = sAh + ar * PSTR + kb;
                const __half* aq = sAl + ar * PSTR + kb;
                uint32_t ah[4], al[4];
                ah[0] = *(const uint32_t*)ap;
                ah[1] = *(const uint32_t*)(ap + 8 * PSTR);
                ah[2] = *(const uint32_t*)(ap + 8);
                ah[3] = *(const uint32_t*)(ap + 8 * PSTR + 8);
                al[0] = *(const uint32_t*)aq;
                al[1] = *(const uint32_t*)(aq + 8 * PSTR);
                al[2] = *(const uint32_t*)(aq + 8);
                al[3] = *(const uint32_t*)(aq + 8 * PSTR + 8);
#pragma unroll
                for (int nt = 0; nt < 8; nt++) {
                    mma16(C[mt][nt], ah, bh[nt]);
                    mma16(C[mt][nt], al, bh[nt]);
                }
            }
        }
    }
}

// ---------------- QKV projection with fused RoPE + Q scale -----------------
__global__ void __launch_bounds__(256, 1) qkv_f16_kernel(const float* __restrict__ cosp,
                                                         const float* __restrict__ sinp) {
    extern __shared__ __half smh[];
    const int z = blockIdx.z;
    const int rowBase = blockIdx.y * 128;
    const int colBase = blockIdx.x * 256;

    float C[4][8][4];
#pragma unroll
    for (int a = 0; a < 4; a++)
#pragma unroll
        for (int b = 0; b < 8; b++)
#pragma unroll
            for (int c = 0; c < 4; c++) C[a][b][c] = 0.f;

    proj_mainloop(g_xh + (size_t)rowBase * Dsz, g_xl + (size_t)rowBase * Dsz,
                  g_w + (size_t)z * NW + (size_t)colBase * Dsz, C, smh);

    const int tid = threadIdx.x;
    const int wid = tid >> 5, lane = tid & 31;
    const int g = lane >> 2, t = lane & 3;
    const int wm = (wid >> 2) * 64, wn = (wid & 3) * 64;

    // fused RoPE: cols d and d+32 live in C[mt][nt] / C[mt][nt+4] of this thread
    if (z <= 1) {
#pragma unroll
        for (int mt = 0; mt < 4; mt++) {
            int r = rowBase + wm + mt * 16 + g;
            int l0 = r & (Lsz - 1);
#pragma unroll
            for (int nt = 0; nt < 4; nt++) {
                int d = nt * 8 + 2 * t;
#pragma unroll
                for (int e = 0; e < 4; e++) {
                    int dd = d + (e & 1);
                    int ll = (e < 2) ? l0 : (l0 + 8);
                    float c1 = cosp[ll * HDsz + dd];
                    float s1 = sinp[ll * HDsz + dd];
                    float c2 = cosp[ll * HDsz + dd + 32];
                    float s2 = sinp[ll * HDsz + dd + 32];
                    float x1 = C[mt][nt][e], x2 = C[mt][nt + 4][e];
                    C[mt][nt][e]     = x1 * c1 - x2 * s1;
                    C[mt][nt + 4][e] = x2 * c2 + x1 * s2;
                }
            }
        }
    }
    if (z == 0) {   // fold 1/sqrt(hd) into q (exact power of two)
#pragma unroll
        for (int mt = 0; mt < 4; mt++)
#pragma unroll
            for (int nt = 0; nt < 8; nt++)
#pragma unroll
                for (int e = 0; e < 4; e++) C[mt][nt][e] *= 0.125f;
    }

#pragma unroll
    for (int mt = 0; mt < 4; mt++) {
#pragma unroll
        for (int nt = 0; nt < 8; nt++) {
            int r = rowBase + wm + mt * 16 + g;
            int n = colBase + wn + nt * 8 + 2 * t;
            int h = n >> 6, d = n & 63;
            int b = r >> 11, l = r & 2047;
            size_t o0 = (((size_t)(b * Hsz + h) * Lsz + l) * HDsz + d);
            size_t o1 = (((size_t)(b * Hsz + h) * Lsz + (l + 8)) * HDsz + d);
            if (z == 0) {           // q: split hi/lo
                __half h0, l0h, h1, l1h;
                sh2(C[mt][nt][0], h0, l0h); sh2(C[mt][nt][1], h1, l1h);
                *(uint32_t*)(g_qh + o0) = packh(h0, h1);
                *(uint32_t*)(g_ql + o0) = packh(l0h, l1h);
                sh2(C[mt][nt][2], h0, l0h); sh2(C[mt][nt][3], h1, l1h);
                *(uint32_t*)(g_qh + o1) = packh(h0, h1);
                *(uint32_t*)(g_ql + o1) = packh(l0h, l1h);
            } else {                // k, v: single fp16
                __half* dst = (z == 1) ? g_k : g_v;
                *(uint32_t*)(dst + o0) =
                    packh(__float2half_rn(C[mt][nt][0]), __float2half_rn(C[mt][nt][1]));
                *(uint32_t*)(dst + o1) =
                    packh(__float2half_rn(C[mt][nt][2]), __float2half_rn(C[mt][nt][3]));
            }
        }
    }
}

// ---------------- Output projection (writes fp32 out) ----------------------
__global__ void __launch_bounds__(256, 1) oproj_f16_kernel(float* __restrict__ out) {
    extern __shared__ __half smh[];
    const int rowBase = blockIdx.y * 128;
    const int colBase = blockIdx.x * 256;

    float C[4][8][4];
#pragma unroll
    for (int a = 0; a < 4; a++)
#pragma unroll
        for (int b = 0; b < 8; b++)
#pragma unroll
            for (int c = 0; c < 4; c++) C[a][b][c] = 0.f;

    proj_mainloop(g_aoh + (size_t)rowBase * Dsz, g_aol + (size_t)rowBase * Dsz,
                  g_w + (size_t)3 * NW + (size_t)colBase * Dsz, C, smh);

    const int tid = threadIdx.x;
    const int wid = tid >> 5, lane = tid & 31;
    const int g = lane >> 2, t = lane & 3;
    const int wm = (wid >> 2) * 64, wn = (wid & 3) * 64;
#pragma unroll
    for (int mt = 0; mt < 4; mt++) {
#pragma unroll
        for (int nt = 0; nt < 8; nt++) {
            int r = rowBase + wm + mt * 16 + g;
            int n = colBase + wn + nt * 8 + 2 * t;
            *(float2*)(out + (size_t)r * Dsz + n) = make_float2(C[mt][nt][0], C[mt][nt][1]);
            *(float2*)(out + (size_t)(r + 8) * Dsz + n) = make_float2(C[mt][nt][2], C[mt][nt][3]);
        }
    }
}

// ---------------- Flash attention: fp16, persistent + work queue -----------
// GEMM1: Q split (2 terms). GEMM2: P single fp16 (1 term).
#define FSTRB 72
#define OFF_QH 0
#define OFF_QL (128 * FSTRB)
#define OFF_KV0 (2 * 128 * FSTRB)
#define KV_PLANE (64 * FSTRB)
#define KV_STAGE (2 * KV_PLANE)                  // K single + V single
#define FLASH_ELEMS (OFF_KV0 + 2 * KV_STAGE)
#define FLASH_SMEM (FLASH_ELEMS * 2 + 16)        // +16 for s_item slot

__global__ void __launch_bounds__(256, 2) flashmma_kernel() {
    extern __shared__ __half smh[];
    __half* Qh = smh + OFF_QH;
    __half* Ql = smh + OFF_QL;
    int* s_item = (int*)(smh + FLASH_ELEMS);

    const int tid = threadIdx.x;
    const int wid = tid >> 5, lane = tid & 31;
    const int g = lane >> 2, t = lane & 3;
    const int vln = lane & 15;
    const int pr = wid * 16 + g;

    for (;;) {
        __syncthreads();
        if (tid == 0) *s_item = atomicAdd(&g_wctr, 1);
        __syncthreads();
        const int item = *s_item;
        if (item >= NITEMS) break;

        const int qt = NQT - 1 - (item >> 5);   // biggest-first
        const int bh = item & 31;
        const int q0 = qt * 128;
        const size_t base = (size_t)bh * Lsz * HDsz;

        // ---- Q tile (hi/lo) ----
#pragma unroll
        for (int i = 0; i < 4; i++) {
            int idx = tid + 256 * i;
            int row = idx >> 3;
            int c8 = (idx & 7) * 8;
            size_t go = base + (size_t)(q0 + row) * HDsz + c8;
            *(float4*)(Qh + row * FSTRB + c8) = *(const float4*)(g_qh + go);
            *(float4*)(Ql + row * FSTRB + c8) = *(const float4*)(g_ql + go);
        }

        auto loadKV = [&](int kt2, int s) {
            __half* st = smh + OFF_KV0 + s * KV_STAGE;
            const int j0 = kt2 * 64;
#pragma unroll
            for (int p = 0; p < 2; p++) {
                const __half* gp = (p == 0) ? g_k : g_v;
#pragma unroll
                for (int i = 0; i < 2; i++) {
                    int idx = tid + 256 * i;
                    int row = idx >> 3;
                    int c8 = (idx & 7) * 8;
                    cp16((uint32_t)__cvta_generic_to_shared(st + p * KV_PLANE + row * FSTRB + c8),
                         gp + base + (size_t)(j0 + row) * HDsz + c8);
                }
            }
        };

        float O[8][4];
#pragma unroll
        for (int i = 0; i < 8; i++)
#pragma unroll
            for (int j = 0; j < 4; j++) O[i][j] = 0.f;
        float mr[2] = {-1e30f, -1e30f};
        float lr[2] = {0.f, 0.f};

        const int nkt = 2 * qt + 2;
        loadKV(0, 0); cpcommit();

        for (int kt = 0; kt < nkt; kt++) {
            const int s = kt & 1;
            const int j0 = kt * 64;
            __syncthreads();
            if (kt + 1 < nkt) { loadKV(kt + 1, s ^ 1); cpcommit(); cpwait1(); }
            else              { cpwait0(); }
            __syncthreads();

            const __half* Ks = smh + OFF_KV0 + s * KV_STAGE;
            const __half* Vs = Ks + KV_PLANE;
            const uint32_t v_u32 = (uint32_t)__cvta_generic_to_shared(Vs);

            // ---- GEMM1: S = Q @ K^T (Qh,Ql vs K single) ----
            float S[8][4];
#pragma unroll
            for (int i = 0; i < 8; i++)
#pragma unroll
                for (int j = 0; j < 4; j++) S[i][j] = 0.f;

#pragma unroll
            for (int ks = 0; ks < 4; ks++) {
                const int kb = ks * 16 + 2 * t;
                const __half* ap = Qh + pr * FSTRB + kb;
                const __half* aq = Ql + pr * FSTRB + kb;
                uint32_t ah[4], al[4];
                ah[0] = *(const uint32_t*)ap;
                ah[1] = *(const uint32_t*)(ap + 8 * FSTRB);
                ah[2] = *(const uint32_t*)(ap + 8);
                ah[3] = *(const uint32_t*)(ap + 8 * FSTRB + 8);
                al[0] = *(const uint32_t*)aq;
                al[1] = *(const uint32_t*)(aq + 8 * FSTRB);
                al[2] = *(const uint32_t*)(aq + 8);
                al[3] = *(const uint32_t*)(aq + 8 * FSTRB + 8);
#pragma unroll
                for (int nt = 0; nt < 8; nt++) {
                    const __half* kp = Ks + (nt * 8 + g) * FSTRB + kb;
                    uint32_t bh2[2] = {*(const uint32_t*)kp, *(const uint32_t*)(kp + 8)};
                    mma16(S[nt], ah, bh2);
                    mma16(S[nt], al, bh2);
                }
            }

            // ---- causal mask (diagonal tiles only) ----
            if (kt >= 2 * qt) {
                int r0g = q0 + pr;
#pragma unroll
                for (int nt = 0; nt < 8; nt++) {
                    int c0 = j0 + nt * 8 + 2 * t;
                    if (c0 > r0g)         S[nt][0] = -1e30f;
                    if (c0 + 1 > r0g)     S[nt][1] = -1e30f;
                    if (c0 > r0g + 8)     S[nt][2] = -1e30f;
                    if (c0 + 1 > r0g + 8) S[nt][3] = -1e30f;
                }
            }

            // ---- online softmax ----
#pragma unroll
            for (int h2 = 0; h2 < 2; h2++) {
                float mloc = -1e30f;
#pragma unroll
                for (int nt = 0; nt < 8; nt++)
                    mloc = fmaxf(mloc, fmaxf(S[nt][2 * h2], S[nt][2 * h2 + 1]));
                mloc = fmaxf(mloc, __shfl_xor_sync(0xffffffffu, mloc, 1));
                mloc = fmaxf(mloc, __shfl_xor_sync(0xffffffffu, mloc, 2));
                float mnew = fmaxf(mr[h2], mloc);
                float sc = __expf(mr[h2] - mnew);
                float ls = 0.f;
#pragma unroll
                for (int nt = 0; nt < 8; nt++) {
                    float p0 = __expf(S[nt][2 * h2] - mnew);
                    float p1 = __expf(S[nt][2 * h2 + 1] - mnew);
                    S[nt][2 * h2] = p0; S[nt][2 * h2 + 1] = p1;
                    ls += p0 + p1;
                }
                ls += __shfl_xor_sync(0xffffffffu, ls, 1);
                ls += __shfl_xor_sync(0xffffffffu, ls, 2);
                lr[h2] = lr[h2] * sc + ls;
                mr[h2] = mnew;
#pragma unroll
                for (int nt = 0; nt < 8; nt++) {
                    O[nt][2 * h2] *= sc;
                    O[nt][2 * h2 + 1] *= sc;
                }
            }

            // ---- GEMM2: O += P @ V (P single fp16 from S regs, V single) ----
#pragma unroll
            for (int ks = 0; ks < 4; ks++) {
                uint32_t ah[4];
                ah[0] = packh(__float2half_rn(S[2 * ks][0]), __float2half_rn(S[2 * ks][1]));
                ah[1] = packh(__float2half_rn(S[2 * ks][2]), __float2half_rn(S[2 * ks][3]));
                ah[2] = packh(__float2half_rn(S[2 * ks + 1][0]), __float2half_rn(S[2 * ks + 1][1]));
                ah[3] = packh(__float2half_rn(S[2 * ks + 1][2]), __float2half_rn(S[2 * ks + 1][3]));
                const uint32_t rowoff = ((ks * 16 + vln) * FSTRB) * 2;
#pragma unroll
                for (int dt = 0; dt < 8; dt++) {
                    uint32_t bh2[2];
                    ldsm_x2_trans(bh2[0], bh2[1], v_u32 + rowoff + dt * 16);
                    mma16(O[dt], ah, bh2);
                }
            }
        }

        // ---- epilogue: normalize, split, write ao planes ----
        const float i0 = 1.f / lr[0];
        const float i1 = 1.f / lr[1];
        const int r = q0 + pr;
        const int b = bh >> 4;
        const int h = bh & 15;
        const size_t ob = (size_t)b * Lsz * Dsz + (size_t)h * HDsz;
#pragma unroll
        for (int dt = 0; dt < 8; dt++) {
            int d = dt * 8 + 2 * t;
            __half h0, l0h, h1, l1h;
            sh2(O[dt][0] * i0, h0, l0h); sh2(O[dt][1] * i0, h1, l1h);
            *(uint32_t*)(g_aoh + ob + (size_t)r * Dsz + d) = packh(h0, h1);
            *(uint32_t*)(g_aol + ob + (size_t)r * Dsz + d) = packh(l0h, l1h);
            sh2(O[dt][2] * i1, h0, l0h); sh2(O[dt][3] * i1, h1, l1h);
            *(uint32_t*)(g_aoh + ob + (size_t)(r + 8) * Dsz + d) = packh(h0, h1);
            *(uint32_t*)(g_aol + ob + (size_t)(r + 8) * Dsz + d) = packh(l0h, l1h);
        }
    }
}

// ---------------------------------------------------------------------------
extern "C" void kernel_launch(void* const* d_in, const int* in_sizes, int n_in,
                              void* d_out, int out_size) {
    (void)in_sizes; (void)n_in; (void)out_size;
    const float* x    = (const float*)d_in[0];
    const float* cosp = (const float*)d_in[1];
    const float* sinp = (const float*)d_in[2];
    const float* wq   = (const float*)d_in[3];
    const float* wk   = (const float*)d_in[4];
    const float* wv   = (const float*)d_in[5];
    const float* wo   = (const float*)d_in[6];
    float* out = (float*)d_out;

    cudaFuncSetAttribute(qkv_f16_kernel,
                         cudaFuncAttributeMaxDynamicSharedMemorySize, PROJ_SMEM);
    cudaFuncSetAttribute(oproj_f16_kernel,
                         cudaFuncAttributeMaxDynamicSharedMemorySize, PROJ_SMEM);
    cudaFuncSetAttribute(flashmma_kernel,
                         cudaFuncAttributeMaxDynamicSharedMemorySize, FLASH_SMEM);

    // 1) split inputs (also resets flash work queue)
    split_x_kernel<<<(NX / 2) / 256, 256>>>(x);
    split_w_kernel<<<(4 * NW / 2) / 256, 256>>>(wq, wk, wv, wo);

    // 2) QKV projections with fused RoPE + q-scale -> q (hi/lo), k, v planes
    qkv_f16_kernel<<<dim3(Dsz / 256, (Bsz * Lsz) / 128, 3), 256, PROJ_SMEM>>>(cosp, sinp);

    // 3) causal flash attention (persistent, work-queue balanced) -> ao planes
    flashmma_kernel<<<FLASH_CTAS, 256, FLASH_SMEM>>>();

    // 4) output projection -> d_out
    oproj_f16_kernel<<<dim3(Dsz / 256, (Bsz * Lsz) / 128), 256, PROJ_SMEM>>>(out);
}

// round 15
// speedup vs baseline: 1.2157x; 1.1053x over previous
#include <cuda_runtime.h>
#include <cuda_fp16.h>
#include <math.h>
#include <stdint.h>

// Problem constants: B=2, L=2048, D=1024, H=16, hd=64
#define Bsz 2
#define Lsz 2048
#define Dsz 1024
#define Hsz 16
#define HDsz 64

#define NQKV (Bsz * Hsz * Lsz * HDsz)   // 4194304
#define NX   (Bsz * Lsz * Dsz)          // 4194304
#define NW   (Dsz * Dsz)                // 1048576 = 2^20

#define NQT (Lsz / 128)                 // 16 q-tiles
#define NITEMS (NQT * Bsz * Hsz)        // 512 work items
#define FLASH_CTAS 296                  // 2 per SM x 148 SMs

// ---------------- device scratch ------------------------------------------
__device__ __half g_xh[NX],  g_xl[NX];
__device__ __half g_w[4 * NW];                  // wq,wk,wv,wo single fp16
__device__ __half g_qh[NQKV], g_ql[NQKV];
__device__ __half g_k[NQKV];                    // single fp16 (post-RoPE)
__device__ __half g_v[NQKV];                    // single fp16
__device__ __half g_ao[NX];                     // attention out, single fp16
__device__ int g_wctr;                          // flash work-queue counter

// ---------------- helpers --------------------------------------------------
__device__ __forceinline__ void sh2(float x, __half& h, __half& l) {
    h = __float2half_rn(x);
    l = __float2half_rn(x - __half2float(h));
}
__device__ __forceinline__ uint32_t packh(__half a, __half b) {
    uint16_t au = *(uint16_t*)&a, bu = *(uint16_t*)&b;
    return (uint32_t)au | ((uint32_t)bu << 16);
}

__device__ __forceinline__ void mma16(float c[4], const uint32_t a[4], const uint32_t b[2]) {
    asm volatile(
        "mma.sync.aligned.m16n8k16.row.col.f32.f16.f16.f32 "
        "{%0,%1,%2,%3}, {%4,%5,%6,%7}, {%8,%9}, {%0,%1,%2,%3};\n"
        : "+f"(c[0]), "+f"(c[1]), "+f"(c[2]), "+f"(c[3])
        : "r"(a[0]), "r"(a[1]), "r"(a[2]), "r"(a[3]), "r"(b[0]), "r"(b[1]));
}

__device__ __forceinline__ void ldsm_x2_trans(uint32_t& r0, uint32_t& r1, uint32_t addr) {
    asm volatile("ldmatrix.sync.aligned.m8n8.x2.trans.shared.b16 {%0,%1}, [%2];"
                 : "=r"(r0), "=r"(r1) : "r"(addr));
}

__device__ __forceinline__ void cp16(uint32_t dst, const void* src) {
    asm volatile("cp.async.cg.shared.global [%0],[%1],16;\n" ::"r"(dst), "l"(src) : "memory");
}
__device__ __forceinline__ void cpcommit() { asm volatile("cp.async.commit_group;\n" ::: "memory"); }
__device__ __forceinline__ void cpwait1()  { asm volatile("cp.async.wait_group 1;\n" ::: "memory"); }
__device__ __forceinline__ void cpwait0()  { asm volatile("cp.async.wait_group 0;\n" ::: "memory"); }

// ---------------- split kernels -------------------------------------------
__global__ void split_x_kernel(const float* __restrict__ in) {
    int i = blockIdx.x * blockDim.x + threadIdx.x;
    if (i == 0) g_wctr = 0;             // reset flash work queue every launch
    float2 v = *(const float2*)(in + 2 * (size_t)i);
    __half h0, l0, h1, l1;
    sh2(v.x, h0, l0); sh2(v.y, h1, l1);
    ((uint32_t*)g_xh)[i] = packh(h0, h1);
    ((uint32_t*)g_xl)[i] = packh(l0, l1);
}

__global__ void split_w_kernel(const float* __restrict__ wq,
                               const float* __restrict__ wk,
                               const float* __restrict__ wv,
                               const float* __restrict__ wo) {
    int i = blockIdx.x * blockDim.x + threadIdx.x;
    size_t e = 2 * (size_t)i;
    int m = (int)(e >> 20);
    int r = (int)(e & (NW - 1));
    const float* src = (m == 0) ? wq : (m == 1) ? wk : (m == 2) ? wv : wo;
    float2 v = *(const float2*)(src + r);
    ((uint32_t*)g_w)[((size_t)m * NW + r) >> 1] =
        packh(__float2half_rn(v.x), __float2half_rn(v.y));
}

// ---------------- fp16 projection GEMM (128x256 CTA, 256 threads) ----------
// SPLIT=true:  C = (Ah + Al) @ B^T  (2 mma terms, A exact)
// SPLIT=false: C = Ah @ B^T         (1 mma term,  A rounded)
#define PSTR 40
#define PA_ELEMS (128 * PSTR)                     // 5120
#define PB_ELEMS (256 * PSTR)                     // 10240
#define PSTAGE_ELEMS (2 * PA_ELEMS + PB_ELEMS)    // 20480 halves
#define PSTAGE_BYTES (PSTAGE_ELEMS * 2)           // 40960
#define PROJ_SMEM (3 * PSTAGE_BYTES)              // 122880 bytes

template <bool SPLIT>
__device__ __forceinline__ void proj_mainloop(const __half* __restrict__ Agh,
                                              const __half* __restrict__ Agl,
                                              const __half* __restrict__ Bg,
                                              float C[4][8][4], __half* sm) {
    const int tid = threadIdx.x;
    const int wid = tid >> 5, lane = tid & 31;
    const int g = lane >> 2, t = lane & 3;
    const int wm = (wid >> 2) * 64;
    const int wn = (wid & 3) * 64;

    auto load_chunk = [&](int c, int s) {
        __half* st = sm + s * PSTAGE_ELEMS;
        // A hi plane (always)
        {
            __half* sp = st;
#pragma unroll
            for (int i = 0; i < 2; i++) {
                int idx = tid + 256 * i;
                int row = idx >> 2, q = idx & 3;
                cp16((uint32_t)__cvta_generic_to_shared(sp + row * PSTR + q * 8),
                     Agh + (size_t)row * Dsz + c * 32 + q * 8);
            }
        }
        // A lo plane (split only)
        if (SPLIT) {
            __half* sp = st + PA_ELEMS;
#pragma unroll
            for (int i = 0; i < 2; i++) {
                int idx = tid + 256 * i;
                int row = idx >> 2, q = idx & 3;
                cp16((uint32_t)__cvta_generic_to_shared(sp + row * PSTR + q * 8),
                     Agl + (size_t)row * Dsz + c * 32 + q * 8);
            }
        }
        // B plane
        {
            __half* sp = st + 2 * PA_ELEMS;
#pragma unroll
            for (int i = 0; i < 4; i++) {
                int idx = tid + 256 * i;
                int row = idx >> 2, q = idx & 3;
                cp16((uint32_t)__cvta_generic_to_shared(sp + row * PSTR + q * 8),
                     Bg + (size_t)row * Dsz + c * 32 + q * 8);
            }
        }
    };

    const int NCH = Dsz / 32;
    load_chunk(0, 0); cpcommit();
    load_chunk(1, 1); cpcommit();

    for (int c = 0; c < NCH; c++) {
        if (c == NCH - 1) cpwait0(); else cpwait1();
        __syncthreads();
        if (c + 2 < NCH) { load_chunk(c + 2, (c + 2) % 3); cpcommit(); }

        const __half* st = sm + (c % 3) * PSTAGE_ELEMS;
        const __half* sAh = st;
        const __half* sAl = st + PA_ELEMS;
        const __half* sB  = st + 2 * PA_ELEMS;

#pragma unroll
        for (int ks = 0; ks < 2; ks++) {
            const int kb = ks * 16 + 2 * t;
            uint32_t bh[8][2];
#pragma unroll
            for (int nt = 0; nt < 8; nt++) {
                const __half* bp = sB + (wn + nt * 8 + g) * PSTR + kb;
                bh[nt][0] = *(const uint32_t*)bp;
                bh[nt][1] = *(const uint32_t*)(bp + 8);
            }
#pragma unroll
            for (int mt = 0; mt < 4; mt++) {
                const int ar = wm + mt * 16 + g;
                const __half* ap = sAh + ar * PSTR + kb;
                uint32_t ah[4];
                ah[0] = *(const uint32_t*)ap;
                ah[1] = *(const uint32_t*)(ap + 8 * PSTR);
                ah[2] = *(const uint32_t*)(ap + 8);
                ah[3] = *(const uint32_t*)(ap + 8 * PSTR + 8);
                uint32_t al[4];
                if (SPLIT) {
                    const __half* aq = sAl + ar * PSTR + kb;
                    al[0] = *(const uint32_t*)aq;
                    al[1] = *(const uint32_t*)(aq + 8 * PSTR);
                    al[2] = *(const uint32_t*)(aq + 8);
                    al[3] = *(const uint32_t*)(aq + 8 * PSTR + 8);
                }
#pragma unroll
                for (int nt = 0; nt < 8; nt++) {
                    mma16(C[mt][nt], ah, bh[nt]);
                    if (SPLIT) mma16(C[mt][nt], al, bh[nt]);
                }
            }
        }
    }
}

// ---------------- QKV projection with fused RoPE + Q scale -----------------
// q,k: 2-term (score path, keep exact x). v: 1-term (linear path).
__global__ void __launch_bounds__(256, 1) qkv_f16_kernel(const float* __restrict__ cosp,
                                                         const float* __restrict__ sinp) {
    extern __shared__ __half smh[];
    const int z = blockIdx.z;
    const int rowBase = blockIdx.y * 128;
    const int colBase = blockIdx.x * 256;

    float C[4][8][4];
#pragma unroll
    for (int a = 0; a < 4; a++)
#pragma unroll
        for (int b = 0; b < 8; b++)
#pragma unroll
            for (int c = 0; c < 4; c++) C[a][b][c] = 0.f;

    if (z == 2) {
        proj_mainloop<false>(g_xh + (size_t)rowBase * Dsz, g_xl + (size_t)rowBase * Dsz,
                             g_w + (size_t)2 * NW + (size_t)colBase * Dsz, C, smh);
    } else {
        proj_mainloop<true>(g_xh + (size_t)rowBase * Dsz, g_xl + (size_t)rowBase * Dsz,
                            g_w + (size_t)z * NW + (size_t)colBase * Dsz, C, smh);
    }

    const int tid = threadIdx.x;
    const int wid = tid >> 5, lane = tid & 31;
    const int g = lane >> 2, t = lane & 3;
    const int wm = (wid >> 2) * 64, wn = (wid & 3) * 64;

    // fused RoPE: cols d and d+32 live in C[mt][nt] / C[mt][nt+4] of this thread
    if (z <= 1) {
#pragma unroll
        for (int mt = 0; mt < 4; mt++) {
            int r = rowBase + wm + mt * 16 + g;
            int l0 = r & (Lsz - 1);
#pragma unroll
            for (int nt = 0; nt < 4; nt++) {
                int d = nt * 8 + 2 * t;
#pragma unroll
                for (int e = 0; e < 4; e++) {
                    int dd = d + (e & 1);
                    int ll = (e < 2) ? l0 : (l0 + 8);
                    float c1 = cosp[ll * HDsz + dd];
                    float s1 = sinp[ll * HDsz + dd];
                    float c2 = cosp[ll * HDsz + dd + 32];
                    float s2 = sinp[ll * HDsz + dd + 32];
                    float x1 = C[mt][nt][e], x2 = C[mt][nt + 4][e];
                    C[mt][nt][e]     = x1 * c1 - x2 * s1;
                    C[mt][nt + 4][e] = x2 * c2 + x1 * s2;
                }
            }
        }
    }
    if (z == 0) {   // fold 1/sqrt(hd) into q (exact power of two)
#pragma unroll
        for (int mt = 0; mt < 4; mt++)
#pragma unroll
            for (int nt = 0; nt < 8; nt++)
#pragma unroll
                for (int e = 0; e < 4; e++) C[mt][nt][e] *= 0.125f;
    }

#pragma unroll
    for (int mt = 0; mt < 4; mt++) {
#pragma unroll
        for (int nt = 0; nt < 8; nt++) {
            int r = rowBase + wm + mt * 16 + g;
            int n = colBase + wn + nt * 8 + 2 * t;
            int h = n >> 6, d = n & 63;
            int b = r >> 11, l = r & 2047;
            size_t o0 = (((size_t)(b * Hsz + h) * Lsz + l) * HDsz + d);
            size_t o1 = (((size_t)(b * Hsz + h) * Lsz + (l + 8)) * HDsz + d);
            if (z == 0) {           // q: split hi/lo (score path)
                __half h0, l0h, h1, l1h;
                sh2(C[mt][nt][0], h0, l0h); sh2(C[mt][nt][1], h1, l1h);
                *(uint32_t*)(g_qh + o0) = packh(h0, h1);
                *(uint32_t*)(g_ql + o0) = packh(l0h, l1h);
                sh2(C[mt][nt][2], h0, l0h); sh2(C[mt][nt][3], h1, l1h);
                *(uint32_t*)(g_qh + o1) = packh(h0, h1);
                *(uint32_t*)(g_ql + o1) = packh(l0h, l1h);
            } else {                // k, v: single fp16
                __half* dst = (z == 1) ? g_k : g_v;
                *(uint32_t*)(dst + o0) =
                    packh(__float2half_rn(C[mt][nt][0]), __float2half_rn(C[mt][nt][1]));
                *(uint32_t*)(dst + o1) =
                    packh(__float2half_rn(C[mt][nt][2]), __float2half_rn(C[mt][nt][3]));
            }
        }
    }
}

// ---------------- Output projection (single-term, writes fp32 out) ---------
__global__ void __launch_bounds__(256, 1) oproj_f16_kernel(float* __restrict__ out) {
    extern __shared__ __half smh[];
    const int rowBase = blockIdx.y * 128;
    const int colBase = blockIdx.x * 256;

    float C[4][8][4];
#pragma unroll
    for (int a = 0; a < 4; a++)
#pragma unroll
        for (int b = 0; b < 8; b++)
#pragma unroll
            for (int c = 0; c < 4; c++) C[a][b][c] = 0.f;

    proj_mainloop<false>(g_ao + (size_t)rowBase * Dsz, g_ao + (size_t)rowBase * Dsz,
                         g_w + (size_t)3 * NW + (size_t)colBase * Dsz, C, smh);

    const int tid = threadIdx.x;
    const int wid = tid >> 5, lane = tid & 31;
    const int g = lane >> 2, t = lane & 3;
    const int wm = (wid >> 2) * 64, wn = (wid & 3) * 64;
#pragma unroll
    for (int mt = 0; mt < 4; mt++) {
#pragma unroll
        for (int nt = 0; nt < 8; nt++) {
            int r = rowBase + wm + mt * 16 + g;
            int n = colBase + wn + nt * 8 + 2 * t;
            *(float2*)(out + (size_t)r * Dsz + n) = make_float2(C[mt][nt][0], C[mt][nt][1]);
            *(float2*)(out + (size_t)(r + 8) * Dsz + n) = make_float2(C[mt][nt][2], C[mt][nt][3]);
        }
    }
}

// ---------------- Flash attention: fp16, persistent + work queue -----------
// GEMM1: Q split (2 terms). GEMM2: P single fp16 (1 term). ao: single fp16.
#define FSTRB 72
#define OFF_QH 0
#define OFF_QL (128 * FSTRB)
#define OFF_KV0 (2 * 128 * FSTRB)
#define KV_PLANE (64 * FSTRB)
#define KV_STAGE (2 * KV_PLANE)                  // K single + V single
#define FLASH_ELEMS (OFF_KV0 + 2 * KV_STAGE)
#define FLASH_SMEM (FLASH_ELEMS * 2 + 16)        // +16 for s_item slot

__global__ void __launch_bounds__(256, 2) flashmma_kernel() {
    extern __shared__ __half smh[];
    __half* Qh = smh + OFF_QH;
    __half* Ql = smh + OFF_QL;
    int* s_item = (int*)(smh + FLASH_ELEMS);

    const int tid = threadIdx.x;
    const int wid = tid >> 5, lane = tid & 31;
    const int g = lane >> 2, t = lane & 3;
    const int vln = lane & 15;
    const int pr = wid * 16 + g;

    for (;;) {
        __syncthreads();
        if (tid == 0) *s_item = atomicAdd(&g_wctr, 1);
        __syncthreads();
        const int item = *s_item;
        if (item >= NITEMS) break;

        const int qt = NQT - 1 - (item >> 5);   // biggest-first
        const int bh = item & 31;
        const int q0 = qt * 128;
        const size_t base = (size_t)bh * Lsz * HDsz;

        // ---- Q tile (hi/lo) ----
#pragma unroll
        for (int i = 0; i < 4; i++) {
            int idx = tid + 256 * i;
            int row = idx >> 3;
            int c8 = (idx & 7) * 8;
            size_t go = base + (size_t)(q0 + row) * HDsz + c8;
            *(float4*)(Qh + row * FSTRB + c8) = *(const float4*)(g_qh + go);
            *(float4*)(Ql + row * FSTRB + c8) = *(const float4*)(g_ql + go);
        }

        auto loadKV = [&](int kt2, int s) {
            __half* st = smh + OFF_KV0 + s * KV_STAGE;
            const int j0 = kt2 * 64;
#pragma unroll
            for (int p = 0; p < 2; p++) {
                const __half* gp = (p == 0) ? g_k : g_v;
#pragma unroll
                for (int i = 0; i < 2; i++) {
                    int idx = tid + 256 * i;
                    int row = idx >> 3;
                    int c8 = (idx & 7) * 8;
                    cp16((uint32_t)__cvta_generic_to_shared(st + p * KV_PLANE + row * FSTRB + c8),
                         gp + base + (size_t)(j0 + row) * HDsz + c8);
                }
            }
        };

        float O[8][4];
#pragma unroll
        for (int i = 0; i < 8; i++)
#pragma unroll
            for (int j = 0; j < 4; j++) O[i][j] = 0.f;
        float mr[2] = {-1e30f, -1e30f};
        float lr[2] = {0.f, 0.f};

        const int nkt = 2 * qt + 2;
        loadKV(0, 0); cpcommit();

        for (int kt = 0; kt < nkt; kt++) {
            const int s = kt & 1;
            const int j0 = kt * 64;
            __syncthreads();
            if (kt + 1 < nkt) { loadKV(kt + 1, s ^ 1); cpcommit(); cpwait1(); }
            else              { cpwait0(); }
            __syncthreads();

            const __half* Ks = smh + OFF_KV0 + s * KV_STAGE;
            const __half* Vs = Ks + KV_PLANE;
            const uint32_t v_u32 = (uint32_t)__cvta_generic_to_shared(Vs);

            // ---- GEMM1: S = Q @ K^T (Qh,Ql vs K single) ----
            float S[8][4];
#pragma unroll
            for (int i = 0; i < 8; i++)
#pragma unroll
                for (int j = 0; j < 4; j++) S[i][j] = 0.f;

#pragma unroll
            for (int ks = 0; ks < 4; ks++) {
                const int kb = ks * 16 + 2 * t;
                const __half* ap = Qh + pr * FSTRB + kb;
                const __half* aq = Ql + pr * FSTRB + kb;
                uint32_t ah[4], al[4];
                ah[0] = *(const uint32_t*)ap;
                ah[1] = *(const uint32_t*)(ap + 8 * FSTRB);
                ah[2] = *(const uint32_t*)(ap + 8);
                ah[3] = *(const uint32_t*)(ap + 8 * FSTRB + 8);
                al[0] = *(const uint32_t*)aq;
                al[1] = *(const uint32_t*)(aq + 8 * FSTRB);
                al[2] = *(const uint32_t*)(aq + 8);
                al[3] = *(const uint32_t*)(aq + 8 * FSTRB + 8);
#pragma unroll
                for (int nt = 0; nt < 8; nt++) {
                    const __half* kp = Ks + (nt * 8 + g) * FSTRB + kb;
                    uint32_t bh2[2] = {*(const uint32_t*)kp, *(const uint32_t*)(kp + 8)};
                    mma16(S[nt], ah, bh2);
                    mma16(S[nt], al, bh2);
                }
            }

            // ---- causal mask (diagonal tiles only) ----
            if (kt >= 2 * qt) {
                int r0g = q0 + pr;
#pragma unroll
                for (int nt = 0; nt < 8; nt++) {
                    int c0 = j0 + nt * 8 + 2 * t;
                    if (c0 > r0g)         S[nt][0] = -1e30f;
                    if (c0 + 1 > r0g)     S[nt][1] = -1e30f;
                    if (c0 > r0g + 8)     S[nt][2] = -1e30f;
                    if (c0 + 1 > r0g + 8) S[nt][3] = -1e30f;
                }
            }

            // ---- online softmax ----
#pragma unroll
            for (int h2 = 0; h2 < 2; h2++) {
                float mloc = -1e30f;
#pragma unroll
                for (int nt = 0; nt < 8; nt++)
                    mloc = fmaxf(mloc, fmaxf(S[nt][2 * h2], S[nt][2 * h2 + 1]));
                mloc = fmaxf(mloc, __shfl_xor_sync(0xffffffffu, mloc, 1));
                mloc = fmaxf(mloc, __shfl_xor_sync(0xffffffffu, mloc, 2));
                float mnew = fmaxf(mr[h2], mloc);
                float sc = __expf(mr[h2] - mnew);
                float ls = 0.f;
#pragma unroll
                for (int nt = 0; nt < 8; nt++) {
                    float p0 = __expf(S[nt][2 * h2] - mnew);
                    float p1 = __expf(S[nt][2 * h2 + 1] - mnew);
                    S[nt][2 * h2] = p0; S[nt][2 * h2 + 1] = p1;
                    ls += p0 + p1;
                }
                ls += __shfl_xor_sync(0xffffffffu, ls, 1);
                ls += __shfl_xor_sync(0xffffffffu, ls, 2);
                lr[h2] = lr[h2] * sc + ls;
                mr[h2] = mnew;
#pragma unroll
                for (int nt = 0; nt < 8; nt++) {
                    O[nt][2 * h2] *= sc;
                    O[nt][2 * h2 + 1] *= sc;
                }
            }

            // ---- GEMM2: O += P @ V (P single fp16 from S regs, V single) ----
#pragma unroll
            for (int ks = 0; ks < 4; ks++) {
                uint32_t ah[4];
                ah[0] = packh(__float2half_rn(S[2 * ks][0]), __float2half_rn(S[2 * ks][1]));
                ah[1] = packh(__float2half_rn(S[2 * ks][2]), __float2half_rn(S[2 * ks][3]));
                ah[2] = packh(__float2half_rn(S[2 * ks + 1][0]), __float2half_rn(S[2 * ks + 1][1]));
                ah[3] = packh(__float2half_rn(S[2 * ks + 1][2]), __float2half_rn(S[2 * ks + 1][3]));
                const uint32_t rowoff = ((ks * 16 + vln) * FSTRB) * 2;
#pragma unroll
                for (int dt = 0; dt < 8; dt++) {
                    uint32_t bh2[2];
                    ldsm_x2_trans(bh2[0], bh2[1], v_u32 + rowoff + dt * 16);
                    mma16(O[dt], ah, bh2);
                }
            }
        }

        // ---- epilogue: normalize, write ao single-fp16 plane ----
        const float i0 = 1.f / lr[0];
        const float i1 = 1.f / lr[1];
        const int r = q0 + pr;
        const int b = bh >> 4;
        const int h = bh & 15;
        const size_t ob = (size_t)b * Lsz * Dsz + (size_t)h * HDsz;
#pragma unroll
        for (int dt = 0; dt < 8; dt++) {
            int d = dt * 8 + 2 * t;
            *(uint32_t*)(g_ao + ob + (size_t)r * Dsz + d) =
                packh(__float2half_rn(O[dt][0] * i0), __float2half_rn(O[dt][1] * i0));
            *(uint32_t*)(g_ao + ob + (size_t)(r + 8) * Dsz + d) =
                packh(__float2half_rn(O[dt][2] * i1), __float2half_rn(O[dt][3] * i1));
        }
    }
}

// ---------------------------------------------------------------------------
extern "C" void kernel_launch(void* const* d_in, const int* in_sizes, int n_in,
                              void* d_out, int out_size) {
    (void)in_sizes; (void)n_in; (void)out_size;
    const float* x    = (const float*)d_in[0];
    const float* cosp = (const float*)d_in[1];
    const float* sinp = (const float*)d_in[2];
    const float* wq   = (const float*)d_in[3];
    const float* wk   = (const float*)d_in[4];
    const float* wv   = (const float*)d_in[5];
    const float* wo   = (const float*)d_in[6];
    float* out = (float*)d_out;

    cudaFuncSetAttribute(qkv_f16_kernel,
                         cudaFuncAttributeMaxDynamicSharedMemorySize, PROJ_SMEM);
    cudaFuncSetAttribute(oproj_f16_kernel,
                         cudaFuncAttributeMaxDynamicSharedMemorySize, PROJ_SMEM);
    cudaFuncSetAttribute(flashmma_kernel,
                         cudaFuncAttributeMaxDynamicSharedMemorySize, FLASH_SMEM);

    // 1) split inputs (also resets flash work queue)
    split_x_kernel<<<(NX / 2) / 256, 256>>>(x);
    split_w_kernel<<<(4 * NW / 2) / 256, 256>>>(wq, wk, wv, wo);

    // 2) QKV projections with fused RoPE + q-scale -> q (hi/lo), k, v planes
    qkv_f16_kernel<<<dim3(Dsz / 256, (Bsz * Lsz) / 128, 3), 256, PROJ_SMEM>>>(cosp, sinp);

    // 3) causal flash attention (persistent, work-queue balanced) -> ao plane
    flashmma_kernel<<<FLASH_CTAS, 256, FLASH_SMEM>>>();

    // 4) output projection -> d_out
    oproj_f16_kernel<<<dim3(Dsz / 256, (Bsz * Lsz) / 128), 256, PROJ_SMEM>>>(out);
}

// round 16
// speedup vs baseline: 1.2515x; 1.0295x over previous
#include <cuda_runtime.h>
#include <cuda_fp16.h>
#include <math.h>
#include <stdint.h>

// Problem constants: B=2, L=2048, D=1024, H=16, hd=64
#define Bsz 2
#define Lsz 2048
#define Dsz 1024
#define Hsz 16
#define HDsz 64

#define NQKV (Bsz * Hsz * Lsz * HDsz)   // 4194304
#define NX   (Bsz * Lsz * Dsz)          // 4194304
#define NW   (Dsz * Dsz)                // 1048576 = 2^20

#define NQT (Lsz / 128)                 // 16 q-tiles
#define NITEMS (NQT * Bsz * Hsz)        // 512 work items
#define FLASH_CTAS 296                  // 2 per SM x 148 SMs

// ---------------- device scratch ------------------------------------------
__device__ __half g_xh[NX],  g_xl[NX];
__device__ __half g_w[4 * NW];                  // wq,wk,wv,wo single fp16
__device__ __half g_qh[NQKV], g_ql[NQKV];
__device__ __half g_k[NQKV];                    // single fp16 (post-RoPE)
__device__ __half g_v[NQKV];                    // single fp16
__device__ __half g_ao[NX];                     // attention out, single fp16
__device__ int g_wctr;                          // flash work-queue counter

// ---------------- helpers --------------------------------------------------
__device__ __forceinline__ void sh2(float x, __half& h, __half& l) {
    h = __float2half_rn(x);
    l = __float2half_rn(x - __half2float(h));
}
__device__ __forceinline__ uint32_t packh(__half a, __half b) {
    uint16_t au = *(uint16_t*)&a, bu = *(uint16_t*)&b;
    return (uint32_t)au | ((uint32_t)bu << 16);
}

__device__ __forceinline__ void mma16(float c[4], const uint32_t a[4], const uint32_t b[2]) {
    asm volatile(
        "mma.sync.aligned.m16n8k16.row.col.f32.f16.f16.f32 "
        "{%0,%1,%2,%3}, {%4,%5,%6,%7}, {%8,%9}, {%0,%1,%2,%3};\n"
        : "+f"(c[0]), "+f"(c[1]), "+f"(c[2]), "+f"(c[3])
        : "r"(a[0]), "r"(a[1]), "r"(a[2]), "r"(a[3]), "r"(b[0]), "r"(b[1]));
}

__device__ __forceinline__ void ldsm_x4(uint32_t& r0, uint32_t& r1, uint32_t& r2,
                                        uint32_t& r3, uint32_t addr) {
    asm volatile("ldmatrix.sync.aligned.m8n8.x4.shared.b16 {%0,%1,%2,%3}, [%4];"
                 : "=r"(r0), "=r"(r1), "=r"(r2), "=r"(r3) : "r"(addr));
}
__device__ __forceinline__ void ldsm_x2_trans(uint32_t& r0, uint32_t& r1, uint32_t addr) {
    asm volatile("ldmatrix.sync.aligned.m8n8.x2.trans.shared.b16 {%0,%1}, [%2];"
                 : "=r"(r0), "=r"(r1) : "r"(addr));
}

__device__ __forceinline__ void cp16(uint32_t dst, const void* src) {
    asm volatile("cp.async.cg.shared.global [%0],[%1],16;\n" ::"r"(dst), "l"(src) : "memory");
}
__device__ __forceinline__ void cpcommit() { asm volatile("cp.async.commit_group;\n" ::: "memory"); }
__device__ __forceinline__ void cpwait1()  { asm volatile("cp.async.wait_group 1;\n" ::: "memory"); }
__device__ __forceinline__ void cpwait0()  { asm volatile("cp.async.wait_group 0;\n" ::: "memory"); }

// ---------------- split kernels -------------------------------------------
__global__ void split_x_kernel(const float* __restrict__ in) {
    int i = blockIdx.x * blockDim.x + threadIdx.x;
    if (i == 0) g_wctr = 0;             // reset flash work queue every launch
    float2 v = *(const float2*)(in + 2 * (size_t)i);
    __half h0, l0, h1, l1;
    sh2(v.x, h0, l0); sh2(v.y, h1, l1);
    ((uint32_t*)g_xh)[i] = packh(h0, h1);
    ((uint32_t*)g_xl)[i] = packh(l0, l1);
}

__global__ void split_w_kernel(const float* __restrict__ wq,
                               const float* __restrict__ wk,
                               const float* __restrict__ wv,
                               const float* __restrict__ wo) {
    int i = blockIdx.x * blockDim.x + threadIdx.x;
    size_t e = 2 * (size_t)i;
    int m = (int)(e >> 20);
    int r = (int)(e & (NW - 1));
    const float* src = (m == 0) ? wq : (m == 1) ? wk : (m == 2) ? wv : wo;
    float2 v = *(const float2*)(src + r);
    ((uint32_t*)g_w)[((size_t)m * NW + r) >> 1] =
        packh(__float2half_rn(v.x), __float2half_rn(v.y));
}

// ---------------- fp16 projection GEMM (128x256 CTA, 256 threads) ----------
// ldmatrix.x4 fragment loads. SPLIT=true: 2 mma terms; false: 1 term.
#define PSTR 40
#define PA_ELEMS (128 * PSTR)                     // 5120
#define PB_ELEMS (256 * PSTR)                     // 10240
#define PSTAGE_ELEMS (2 * PA_ELEMS + PB_ELEMS)    // 20480 halves
#define PSTAGE_BYTES (PSTAGE_ELEMS * 2)           // 40960
#define PROJ_SMEM (3 * PSTAGE_BYTES)              // 122880 bytes

template <bool SPLIT>
__device__ __forceinline__ void proj_mainloop(const __half* __restrict__ Agh,
                                              const __half* __restrict__ Agl,
                                              const __half* __restrict__ Bg,
                                              float C[4][8][4], __half* sm) {
    const int tid = threadIdx.x;
    const int wid = tid >> 5, lane = tid & 31;
    const int wm = (wid >> 2) * 64;
    const int wn = (wid & 3) * 64;

    // ldmatrix lane-address components (bytes)
    const int a_row = (lane & 7) | (lane & 8);          // 0..15
    const int a_colh = (lane >> 4) << 3;                // 0 or 8 halves
    const uint32_t aoff = ((wm + a_row) * PSTR + a_colh) * 2;
    const int b_sel = (lane >> 3) & 3;
    const int b_row = lane & 7;
    const uint32_t boff = ((wn + ((b_sel >> 1) << 3) + b_row) * PSTR + ((b_sel & 1) << 3)) * 2;

    auto load_chunk = [&](int c, int s) {
        __half* st = sm + s * PSTAGE_ELEMS;
        {
            __half* sp = st;
#pragma unroll
            for (int i = 0; i < 2; i++) {
                int idx = tid + 256 * i;
                int row = idx >> 2, q = idx & 3;
                cp16((uint32_t)__cvta_generic_to_shared(sp + row * PSTR + q * 8),
                     Agh + (size_t)row * Dsz + c * 32 + q * 8);
            }
        }
        if (SPLIT) {
            __half* sp = st + PA_ELEMS;
#pragma unroll
            for (int i = 0; i < 2; i++) {
                int idx = tid + 256 * i;
                int row = idx >> 2, q = idx & 3;
                cp16((uint32_t)__cvta_generic_to_shared(sp + row * PSTR + q * 8),
                     Agl + (size_t)row * Dsz + c * 32 + q * 8);
            }
        }
        {
            __half* sp = st + 2 * PA_ELEMS;
#pragma unroll
            for (int i = 0; i < 4; i++) {
                int idx = tid + 256 * i;
                int row = idx >> 2, q = idx & 3;
                cp16((uint32_t)__cvta_generic_to_shared(sp + row * PSTR + q * 8),
                     Bg + (size_t)row * Dsz + c * 32 + q * 8);
            }
        }
    };

    const int NCH = Dsz / 32;
    load_chunk(0, 0); cpcommit();
    load_chunk(1, 1); cpcommit();

    for (int c = 0; c < NCH; c++) {
        if (c == NCH - 1) cpwait0(); else cpwait1();
        __syncthreads();
        if (c + 2 < NCH) { load_chunk(c + 2, (c + 2) % 3); cpcommit(); }

        __half* st = sm + (c % 3) * PSTAGE_ELEMS;
        const uint32_t sAh_u = (uint32_t)__cvta_generic_to_shared(st) + aoff;
        const uint32_t sAl_u = sAh_u + PA_ELEMS * 2;
        const uint32_t sB_u  = (uint32_t)__cvta_generic_to_shared(st + 2 * PA_ELEMS) + boff;

#pragma unroll
        for (int ks = 0; ks < 2; ks++) {
            const uint32_t ksb = ks * 32;
            uint32_t bh[8][2];
#pragma unroll
            for (int p = 0; p < 4; p++) {
                ldsm_x4(bh[2 * p][0], bh[2 * p][1], bh[2 * p + 1][0], bh[2 * p + 1][1],
                        sB_u + p * (16 * PSTR * 2) + ksb);
            }
#pragma unroll
            for (int mt = 0; mt < 4; mt++) {
                uint32_t ah[4], al[4];
                ldsm_x4(ah[0], ah[1], ah[2], ah[3], sAh_u + mt * (16 * PSTR * 2) + ksb);
                if (SPLIT)
                    ldsm_x4(al[0], al[1], al[2], al[3], sAl_u + mt * (16 * PSTR * 2) + ksb);
#pragma unroll
                for (int nt = 0; nt < 8; nt++) {
                    mma16(C[mt][nt], ah, bh[nt]);
                    if (SPLIT) mma16(C[mt][nt], al, bh[nt]);
                }
            }
        }
    }
}

// ---------------- QKV projection with fused RoPE + Q scale -----------------
__global__ void __launch_bounds__(256, 1) qkv_f16_kernel(const float* __restrict__ cosp,
                                                         const float* __restrict__ sinp) {
    extern __shared__ __half smh[];
    const int z = blockIdx.z;
    const int rowBase = blockIdx.y * 128;
    const int colBase = blockIdx.x * 256;

    float C[4][8][4];
#pragma unroll
    for (int a = 0; a < 4; a++)
#pragma unroll
        for (int b = 0; b < 8; b++)
#pragma unroll
            for (int c = 0; c < 4; c++) C[a][b][c] = 0.f;

    if (z == 2) {
        proj_mainloop<false>(g_xh + (size_t)rowBase * Dsz, g_xl + (size_t)rowBase * Dsz,
                             g_w + (size_t)2 * NW + (size_t)colBase * Dsz, C, smh);
    } else {
        proj_mainloop<true>(g_xh + (size_t)rowBase * Dsz, g_xl + (size_t)rowBase * Dsz,
                            g_w + (size_t)z * NW + (size_t)colBase * Dsz, C, smh);
    }

    const int tid = threadIdx.x;
    const int wid = tid >> 5, lane = tid & 31;
    const int g = lane >> 2, t = lane & 3;
    const int wm = (wid >> 2) * 64, wn = (wid & 3) * 64;

    // fused RoPE: cols d and d+32 live in C[mt][nt] / C[mt][nt+4] of this thread
    if (z <= 1) {
#pragma unroll
        for (int mt = 0; mt < 4; mt++) {
            int r = rowBase + wm + mt * 16 + g;
            int l0 = r & (Lsz - 1);
#pragma unroll
            for (int nt = 0; nt < 4; nt++) {
                int d = nt * 8 + 2 * t;
#pragma unroll
                for (int e = 0; e < 4; e++) {
                    int dd = d + (e & 1);
                    int ll = (e < 2) ? l0 : (l0 + 8);
                    float c1 = cosp[ll * HDsz + dd];
                    float s1 = sinp[ll * HDsz + dd];
                    float c2 = cosp[ll * HDsz + dd + 32];
                    float s2 = sinp[ll * HDsz + dd + 32];
                    float x1 = C[mt][nt][e], x2 = C[mt][nt + 4][e];
                    C[mt][nt][e]     = x1 * c1 - x2 * s1;
                    C[mt][nt + 4][e] = x2 * c2 + x1 * s2;
                }
            }
        }
    }
    if (z == 0) {   // fold 1/sqrt(hd) into q (exact power of two)
#pragma unroll
        for (int mt = 0; mt < 4; mt++)
#pragma unroll
            for (int nt = 0; nt < 8; nt++)
#pragma unroll
                for (int e = 0; e < 4; e++) C[mt][nt][e] *= 0.125f;
    }

#pragma unroll
    for (int mt = 0; mt < 4; mt++) {
#pragma unroll
        for (int nt = 0; nt < 8; nt++) {
            int r = rowBase + wm + mt * 16 + g;
            int n = colBase + wn + nt * 8 + 2 * t;
            int h = n >> 6, d = n & 63;
            int b = r >> 11, l = r & 2047;
            size_t o0 = (((size_t)(b * Hsz + h) * Lsz + l) * HDsz + d);
            size_t o1 = (((size_t)(b * Hsz + h) * Lsz + (l + 8)) * HDsz + d);
            if (z == 0) {           // q: split hi/lo (score path)
                __half h0, l0h, h1, l1h;
                sh2(C[mt][nt][0], h0, l0h); sh2(C[mt][nt][1], h1, l1h);
                *(uint32_t*)(g_qh + o0) = packh(h0, h1);
                *(uint32_t*)(g_ql + o0) = packh(l0h, l1h);
                sh2(C[mt][nt][2], h0, l0h); sh2(C[mt][nt][3], h1, l1h);
                *(uint32_t*)(g_qh + o1) = packh(h0, h1);
                *(uint32_t*)(g_ql + o1) = packh(l0h, l1h);
            } else {                // k, v: single fp16
                __half* dst = (z == 1) ? g_k : g_v;
                *(uint32_t*)(dst + o0) =
                    packh(__float2half_rn(C[mt][nt][0]), __float2half_rn(C[mt][nt][1]));
                *(uint32_t*)(dst + o1) =
                    packh(__float2half_rn(C[mt][nt][2]), __float2half_rn(C[mt][nt][3]));
            }
        }
    }
}

// ---------------- Output projection (single-term, writes fp32 out) ---------
__global__ void __launch_bounds__(256, 1) oproj_f16_kernel(float* __restrict__ out) {
    extern __shared__ __half smh[];
    const int rowBase = blockIdx.y * 128;
    const int colBase = blockIdx.x * 256;

    float C[4][8][4];
#pragma unroll
    for (int a = 0; a < 4; a++)
#pragma unroll
        for (int b = 0; b < 8; b++)
#pragma unroll
            for (int c = 0; c < 4; c++) C[a][b][c] = 0.f;

    proj_mainloop<false>(g_ao + (size_t)rowBase * Dsz, g_ao + (size_t)rowBase * Dsz,
                         g_w + (size_t)3 * NW + (size_t)colBase * Dsz, C, smh);

    const int tid = threadIdx.x;
    const int wid = tid >> 5, lane = tid & 31;
    const int g = lane >> 2, t = lane & 3;
    const int wm = (wid >> 2) * 64, wn = (wid & 3) * 64;
#pragma unroll
    for (int mt = 0; mt < 4; mt++) {
#pragma unroll
        for (int nt = 0; nt < 8; nt++) {
            int r = rowBase + wm + mt * 16 + g;
            int n = colBase + wn + nt * 8 + 2 * t;
            *(float2*)(out + (size_t)r * Dsz + n) = make_float2(C[mt][nt][0], C[mt][nt][1]);
            *(float2*)(out + (size_t)(r + 8) * Dsz + n) = make_float2(C[mt][nt][2], C[mt][nt][3]);
        }
    }
}

// ---------------- Flash attention: fp16, persistent + work queue -----------
// GEMM1: Q split (2 terms, ldmatrix loads). GEMM2: P single (1 term).
#define FSTRB 72
#define OFF_QH 0
#define OFF_QL (128 * FSTRB)
#define OFF_KV0 (2 * 128 * FSTRB)
#define KV_PLANE (64 * FSTRB)
#define KV_STAGE (2 * KV_PLANE)                  // K single + V single
#define FLASH_ELEMS (OFF_KV0 + 2 * KV_STAGE)
#define FLASH_SMEM (FLASH_ELEMS * 2 + 16)        // +16 for s_item slot

__global__ void __launch_bounds__(256, 2) flashmma_kernel() {
    extern __shared__ __half smh[];
    __half* Qh = smh + OFF_QH;
    __half* Ql = smh + OFF_QL;
    int* s_item = (int*)(smh + FLASH_ELEMS);

    const int tid = threadIdx.x;
    const int wid = tid >> 5, lane = tid & 31;
    const int g = lane >> 2, t = lane & 3;
    const int vln = lane & 15;
    const int pr = wid * 16 + g;

    // ldmatrix lane-address components for GEMM1 (bytes)
    const int a_row = (lane & 7) | (lane & 8);
    const int a_colh = (lane >> 4) << 3;
    const uint32_t qoff = ((wid * 16 + a_row) * FSTRB + a_colh) * 2;
    const int b_sel = (lane >> 3) & 3;
    const int b_row = lane & 7;
    const uint32_t koff = ((((b_sel >> 1) << 3) + b_row) * FSTRB + ((b_sel & 1) << 3)) * 2;

    const uint32_t qh_u = (uint32_t)__cvta_generic_to_shared(Qh) + qoff;
    const uint32_t ql_u = (uint32_t)__cvta_generic_to_shared(Ql) + qoff;

    for (;;) {
        __syncthreads();
        if (tid == 0) *s_item = atomicAdd(&g_wctr, 1);
        __syncthreads();
        const int item = *s_item;
        if (item >= NITEMS) break;

        const int qt = NQT - 1 - (item >> 5);   // biggest-first
        const int bh = item & 31;
        const int q0 = qt * 128;
        const size_t base = (size_t)bh * Lsz * HDsz;

        // ---- Q tile (hi/lo) ----
#pragma unroll
        for (int i = 0; i < 4; i++) {
            int idx = tid + 256 * i;
            int row = idx >> 3;
            int c8 = (idx & 7) * 8;
            size_t go = base + (size_t)(q0 + row) * HDsz + c8;
            *(float4*)(Qh + row * FSTRB + c8) = *(const float4*)(g_qh + go);
            *(float4*)(Ql + row * FSTRB + c8) = *(const float4*)(g_ql + go);
        }

        auto loadKV = [&](int kt2, int s) {
            __half* st = smh + OFF_KV0 + s * KV_STAGE;
            const int j0 = kt2 * 64;
#pragma unroll
            for (int p = 0; p < 2; p++) {
                const __half* gp = (p == 0) ? g_k : g_v;
#pragma unroll
                for (int i = 0; i < 2; i++) {
                    int idx = tid + 256 * i;
                    int row = idx >> 3;
                    int c8 = (idx & 7) * 8;
                    cp16((uint32_t)__cvta_generic_to_shared(st + p * KV_PLANE + row * FSTRB + c8),
                         gp + base + (size_t)(j0 + row) * HDsz + c8);
                }
            }
        };

        float O[8][4];
#pragma unroll
        for (int i = 0; i < 8; i++)
#pragma unroll
            for (int j = 0; j < 4; j++) O[i][j] = 0.f;
        float mr[2] = {-1e30f, -1e30f};
        float lr[2] = {0.f, 0.f};

        const int nkt = 2 * qt + 2;
        loadKV(0, 0); cpcommit();

        for (int kt = 0; kt < nkt; kt++) {
            const int s = kt & 1;
            const int j0 = kt * 64;
            __syncthreads();
            if (kt + 1 < nkt) { loadKV(kt + 1, s ^ 1); cpcommit(); cpwait1(); }
            else              { cpwait0(); }
            __syncthreads();

            const __half* Ks = smh + OFF_KV0 + s * KV_STAGE;
            const __half* Vs = Ks + KV_PLANE;
            const uint32_t k_u = (uint32_t)__cvta_generic_to_shared(Ks) + koff;
            const uint32_t v_u32 = (uint32_t)__cvta_generic_to_shared(Vs);

            // ---- GEMM1: S = Q @ K^T (Qh,Ql vs K single; ldmatrix loads) ----
            float S[8][4];
#pragma unroll
            for (int i = 0; i < 8; i++)
#pragma unroll
                for (int j = 0; j < 4; j++) S[i][j] = 0.f;

#pragma unroll
            for (int ks = 0; ks < 4; ks++) {
                const uint32_t ksb = ks * 32;
                uint32_t ah[4], al[4];
                ldsm_x4(ah[0], ah[1], ah[2], ah[3], qh_u + ksb);
                ldsm_x4(al[0], al[1], al[2], al[3], ql_u + ksb);
#pragma unroll
                for (int p = 0; p < 4; p++) {
                    uint32_t b0[2], b1[2];
                    ldsm_x4(b0[0], b0[1], b1[0], b1[1],
                            k_u + p * (16 * FSTRB * 2) + ksb);
                    mma16(S[2 * p], ah, b0);
                    mma16(S[2 * p], al, b0);
                    mma16(S[2 * p + 1], ah, b1);
                    mma16(S[2 * p + 1], al, b1);
                }
            }

            // ---- causal mask (diagonal tiles only) ----
            if (kt >= 2 * qt) {
                int r0g = q0 + pr;
#pragma unroll
                for (int nt = 0; nt < 8; nt++) {
                    int c0 = j0 + nt * 8 + 2 * t;
                    if (c0 > r0g)         S[nt][0] = -1e30f;
                    if (c0 + 1 > r0g)     S[nt][1] = -1e30f;
                    if (c0 > r0g + 8)     S[nt][2] = -1e30f;
                    if (c0 + 1 > r0g + 8) S[nt][3] = -1e30f;
                }
            }

            // ---- online softmax ----
#pragma unroll
            for (int h2 = 0; h2 < 2; h2++) {
                float mloc = -1e30f;
#pragma unroll
                for (int nt = 0; nt < 8; nt++)
                    mloc = fmaxf(mloc, fmaxf(S[nt][2 * h2], S[nt][2 * h2 + 1]));
                mloc = fmaxf(mloc, __shfl_xor_sync(0xffffffffu, mloc, 1));
                mloc = fmaxf(mloc, __shfl_xor_sync(0xffffffffu, mloc, 2));
                float mnew = fmaxf(mr[h2], mloc);
                float sc = __expf(mr[h2] - mnew);
                float ls = 0.f;
#pragma unroll
                for (int nt = 0; nt < 8; nt++) {
                    float p0 = __expf(S[nt][2 * h2] - mnew);
                    float p1 = __expf(S[nt][2 * h2 + 1] - mnew);
                    S[nt][2 * h2] = p0; S[nt][2 * h2 + 1] = p1;
                    ls += p0 + p1;
                }
                ls += __shfl_xor_sync(0xffffffffu, ls, 1);
                ls += __shfl_xor_sync(0xffffffffu, ls, 2);
                lr[h2] = lr[h2] * sc + ls;
                mr[h2] = mnew;
#pragma unroll
                for (int nt = 0; nt < 8; nt++) {
                    O[nt][2 * h2] *= sc;
                    O[nt][2 * h2 + 1] *= sc;
                }
            }

            // ---- GEMM2: O += P @ V (P single fp16 from S regs, V single) ----
#pragma unroll
            for (int ks = 0; ks < 4; ks++) {
                uint32_t ah[4];
                ah[0] = packh(__float2half_rn(S[2 * ks][0]), __float2half_rn(S[2 * ks][1]));
                ah[1] = packh(__float2half_rn(S[2 * ks][2]), __float2half_rn(S[2 * ks][3]));
                ah[2] = packh(__float2half_rn(S[2 * ks + 1][0]), __float2half_rn(S[2 * ks + 1][1]));
                ah[3] = packh(__float2half_rn(S[2 * ks + 1][2]), __float2half_rn(S[2 * ks + 1][3]));
                const uint32_t rowoff = ((ks * 16 + vln) * FSTRB) * 2;
#pragma unroll
                for (int dt = 0; dt < 8; dt++) {
                    uint32_t bh2[2];
                    ldsm_x2_trans(bh2[0], bh2[1], v_u32 + rowoff + dt * 16);
                    mma16(O[dt], ah, bh2);
                }
            }
        }

        // ---- epilogue: normalize, write ao single-fp16 plane ----
        const float i0 = 1.f / lr[0];
        const float i1 = 1.f / lr[1];
        const int r = q0 + pr;
        const int b = bh >> 4;
        const int h = bh & 15;
        const size_t ob = (size_t)b * Lsz * Dsz + (size_t)h * HDsz;
#pragma unroll
        for (int dt = 0; dt < 8; dt++) {
            int d = dt * 8 + 2 * t;
            *(uint32_t*)(g_ao + ob + (size_t)r * Dsz + d) =
                packh(__float2half_rn(O[dt][0] * i0), __float2half_rn(O[dt][1] * i0));
            *(uint32_t*)(g_ao + ob + (size_t)(r + 8) * Dsz + d) =
                packh(__float2half_rn(O[dt][2] * i1), __float2half_rn(O[dt][3] * i1));
        }
    }
}

// ---------------------------------------------------------------------------
extern "C" void kernel_launch(void* const* d_in, const int* in_sizes, int n_in,
                              void* d_out, int out_size) {
    (void)in_sizes; (void)n_in; (void)out_size;
    const float* x    = (const float*)d_in[0];
    const float* cosp = (const float*)d_in[1];
    const float* sinp = (const float*)d_in[2];
    const float* wq   = (const float*)d_in[3];
    const float* wk   = (const float*)d_in[4];
    const float* wv   = (const float*)d_in[5];
    const float* wo   = (const float*)d_in[6];
    float* out = (float*)d_out;

    cudaFuncSetAttribute(qkv_f16_kernel,
                         cudaFuncAttributeMaxDynamicSharedMemorySize, PROJ_SMEM);
    cudaFuncSetAttribute(oproj_f16_kernel,
                         cudaFuncAttributeMaxDynamicSharedMemorySize, PROJ_SMEM);
    cudaFuncSetAttribute(flashmma_kernel,
                         cudaFuncAttributeMaxDynamicSharedMemorySize, FLASH_SMEM);

    // 1) split inputs (also resets flash work queue)
    split_x_kernel<<<(NX / 2) / 256, 256>>>(x);
    split_w_kernel<<<(4 * NW / 2) / 256, 256>>>(wq, wk, wv, wo);

    // 2) QKV projections with fused RoPE + q-scale -> q (hi/lo), k, v planes
    qkv_f16_kernel<<<dim3(Dsz / 256, (Bsz * Lsz) / 128, 3), 256, PROJ_SMEM>>>(cosp, sinp);

    // 3) causal flash attention (persistent, work-queue balanced) -> ao plane
    flashmma_kernel<<<FLASH_CTAS, 256, FLASH_SMEM>>>();

    // 4) output projection -> d_out
    oproj_f16_kernel<<<dim3(Dsz / 256, (Bsz * Lsz) / 128), 256, PROJ_SMEM>>>(out);
}